// round 2
// baseline (speedup 1.0000x reference)
#include <cuda_runtime.h>
#include <math.h>

// Problem constants
#define Bz   2
#define Sn   2048
#define DM   2048
#define NHn  16
#define HD   128
#define NHHD 2048   // NHn*HD

// ------------------- scratch (device globals; no allocation) -------------------
__device__ float g_q   [(size_t)Bz*Sn*NHHD];
__device__ float g_k   [(size_t)Bz*Sn*NHHD];
__device__ float g_v   [(size_t)Bz*Sn*NHHD];
__device__ float g_attn[(size_t)Bz*Sn*NHHD];
__device__ float g_q1  [Bz*NHHD];
__device__ float g_k1  [Bz*NHHD];
__device__ float g_v1  [Bz*NHHD];
__device__ float g_qkv1[Bz*NHHD];

// ------------------- generic tiled SGEMM -------------------
// C[M,N] = A[M,K] @ B  where B is [K,N] (TRANSB=false) or [N,K] (TRANSB=true, C=A@B^T)
// Requires K % 32 == 0, N % 64 == 0 (true for all our uses). M may be ragged.
template<bool TRANSB>
__global__ __launch_bounds__(256)
void gemm64_kernel(const float* __restrict__ A, const float* __restrict__ Bm,
                   float* __restrict__ C, int M, int N, int K)
{
    const int BM = 64, BN = 64, BK = 32;
    __shared__ float As[BK][BM + 4];
    __shared__ float Bs[BK][BN + 4];

    int tid = threadIdx.x;
    int m0 = blockIdx.y * BM;
    int n0 = blockIdx.x * BN;
    int tx = tid & 15;   // N direction
    int ty = tid >> 4;   // M direction

    float acc[4][4];
#pragma unroll
    for (int i = 0; i < 4; i++)
#pragma unroll
        for (int j = 0; j < 4; j++) acc[i][j] = 0.f;

    for (int k0 = 0; k0 < K; k0 += BK) {
        // --- load A tile (BM x BK), store transposed As[k][m]
#pragma unroll
        for (int it = 0; it < 2; it++) {
            int idx = tid + it * 256;          // 0..511 float4 slots
            int m  = idx >> 3;
            int k4 = (idx & 7) * 4;
            float4 a;
            if (m0 + m < M) a = *(const float4*)&A[(size_t)(m0 + m) * K + k0 + k4];
            else            a = make_float4(0.f, 0.f, 0.f, 0.f);
            As[k4 + 0][m] = a.x;
            As[k4 + 1][m] = a.y;
            As[k4 + 2][m] = a.z;
            As[k4 + 3][m] = a.w;
        }
        // --- load B tile into Bs[k][n]
        if (!TRANSB) {
#pragma unroll
            for (int it = 0; it < 2; it++) {
                int idx = tid + it * 256;
                int kk = idx >> 4;
                int n4 = (idx & 15) * 4;
                float4 b = *(const float4*)&Bm[(size_t)(k0 + kk) * N + n0 + n4];
                *(float4*)&Bs[kk][n4] = b;
            }
        } else {
#pragma unroll
            for (int it = 0; it < 2; it++) {
                int idx = tid + it * 256;
                int n  = idx >> 3;
                int k4 = (idx & 7) * 4;
                float4 b = *(const float4*)&Bm[(size_t)(n0 + n) * K + k0 + k4];
                Bs[k4 + 0][n] = b.x;
                Bs[k4 + 1][n] = b.y;
                Bs[k4 + 2][n] = b.z;
                Bs[k4 + 3][n] = b.w;
            }
        }
        __syncthreads();

#pragma unroll
        for (int kk = 0; kk < BK; kk++) {
            float4 av = *(const float4*)&As[kk][ty * 4];
            float4 bv = *(const float4*)&Bs[kk][tx * 4];
            float a_[4] = {av.x, av.y, av.z, av.w};
            float b_[4] = {bv.x, bv.y, bv.z, bv.w};
#pragma unroll
            for (int i = 0; i < 4; i++)
#pragma unroll
                for (int j = 0; j < 4; j++) acc[i][j] += a_[i] * b_[j];
        }
        __syncthreads();
    }

#pragma unroll
    for (int i = 0; i < 4; i++) {
        int m = m0 + ty * 4 + i;
        if (m < M) {
            float4 o = make_float4(acc[i][0], acc[i][1], acc[i][2], acc[i][3]);
            *(float4*)&C[(size_t)m * N + n0 + tx * 4] = o;
        }
    }
}

// ------------------- flash attention prefill (causal) -------------------
// Q,K,V: [B, S, NH, HD] fp32. O: same layout.
// Block = (query tile of 64, head, batch). 256 threads.
#define BQ  64
#define HDP 132   // padded HD row stride in smem
#define SP  68    // padded score row stride

__global__ __launch_bounds__(256)
void flash_prefill_kernel(const float* __restrict__ Q, const float* __restrict__ Kc,
                          const float* __restrict__ Vc, float* __restrict__ O)
{
    extern __shared__ float sm[];
    float* Qs = sm;                    // BQ * HDP
    float* Ks = Qs + BQ * HDP;         // BQ * HDP
    float* Vs = Ks + BQ * HDP;         // BQ * HDP
    float* Ss = Vs + BQ * HDP;         // BQ * SP

    int tid = threadIdx.x;
    int qt = blockIdx.x, n = blockIdx.y, b = blockIdx.z;
    int q0 = qt * BQ;
    const float scale = 0.08838834764831845f;  // 1/sqrt(128)

    // load Q tile
#pragma unroll
    for (int it = 0; it < 8; it++) {
        int idx = tid + it * 256;            // float4 index, 2048 total
        int r  = idx >> 5;
        int c4 = (idx & 31) * 4;
        float4 v = *(const float4*)&Q[(((size_t)b * Sn + q0 + r) * NHn + n) * HD + c4];
        *(float4*)&Qs[r * HDP + c4] = v;
    }

    int r  = tid >> 2;   // query row within tile (0..63)
    int cg = tid & 3;    // 4-thread group id within row

    float o[32];
#pragma unroll
    for (int i = 0; i < 32; i++) o[i] = 0.f;
    float m = -1e30f, l = 0.f;

    for (int kt = 0; kt <= qt; kt++) {
        int k0 = kt * BQ;
        __syncthreads();   // previous iteration done with Ks/Vs
        // load K/V tiles
#pragma unroll
        for (int it = 0; it < 8; it++) {
            int idx = tid + it * 256;
            int rr = idx >> 5;
            int c4 = (idx & 31) * 4;
            size_t gofs = (((size_t)b * Sn + k0 + rr) * NHn + n) * HD + c4;
            *(float4*)&Ks[rr * HDP + c4] = *(const float4*)&Kc[gofs];
            *(float4*)&Vs[rr * HDP + c4] = *(const float4*)&Vc[gofs];
        }
        __syncthreads();

        // --- S = Q K^T for this thread's 16 columns j = cg + 4*jj
        float sv[16];
#pragma unroll
        for (int jj = 0; jj < 16; jj++) sv[jj] = 0.f;
        for (int d = 0; d < HD; d += 4) {
            float4 qv = *(const float4*)&Qs[r * HDP + d];
#pragma unroll
            for (int jj = 0; jj < 16; jj++) {
                int j = cg + 4 * jj;
                float4 kv = *(const float4*)&Ks[j * HDP + d];
                sv[jj] += qv.x * kv.x + qv.y * kv.y + qv.z * kv.z + qv.w * kv.w;
            }
        }

        // --- scale + causal mask
#pragma unroll
        for (int jj = 0; jj < 16; jj++) {
            int j = cg + 4 * jj;
            bool valid = (k0 + j) <= (q0 + r);
            sv[jj] = valid ? sv[jj] * scale : -1e30f;
        }

        // --- online softmax (4 threads per row cooperate via shuffles)
        float tmax = sv[0];
#pragma unroll
        for (int jj = 1; jj < 16; jj++) tmax = fmaxf(tmax, sv[jj]);
        tmax = fmaxf(tmax, __shfl_xor_sync(0xffffffffu, tmax, 1));
        tmax = fmaxf(tmax, __shfl_xor_sync(0xffffffffu, tmax, 2));
        float mnew = fmaxf(m, tmax);

        float lsum = 0.f;
#pragma unroll
        for (int jj = 0; jj < 16; jj++) {
            float p = __expf(sv[jj] - mnew);
            sv[jj] = p;
            lsum += p;
        }
        lsum += __shfl_xor_sync(0xffffffffu, lsum, 1);
        lsum += __shfl_xor_sync(0xffffffffu, lsum, 2);

        float alpha = __expf(m - mnew);
        m = mnew;
        l = l * alpha + lsum;
#pragma unroll
        for (int i = 0; i < 32; i++) o[i] *= alpha;

        // store P to smem
#pragma unroll
        for (int jj = 0; jj < 16; jj++) Ss[r * SP + cg + 4 * jj] = sv[jj];
        __syncwarp();   // row's 4 producers are in the same warp

        // --- O += P @ V  (thread covers cols (cg+4*cc)*4 .. +3, cc=0..7)
#pragma unroll 4
        for (int j = 0; j < BQ; j++) {
            float p = Ss[r * SP + j];
#pragma unroll
            for (int cc = 0; cc < 8; cc++) {
                float4 vv = *(const float4*)&Vs[j * HDP + (cg + 4 * cc) * 4];
                o[cc * 4 + 0] += p * vv.x;
                o[cc * 4 + 1] += p * vv.y;
                o[cc * 4 + 2] += p * vv.z;
                o[cc * 4 + 3] += p * vv.w;
            }
        }
    }

    float inv = 1.f / l;
    size_t obase = (((size_t)b * Sn + q0 + r) * NHn + n) * HD;
#pragma unroll
    for (int cc = 0; cc < 8; cc++) {
        float4 ov = make_float4(o[cc * 4 + 0] * inv, o[cc * 4 + 1] * inv,
                                o[cc * 4 + 2] * inv, o[cc * 4 + 3] * inv);
        *(float4*)&O[obase + (size_t)(cg + 4 * cc) * 4] = ov;
    }
}

// ------------------- decode attention -------------------
// One block per (head, batch). Attends q1 over K cache (S keys) + k1 (1 key).
__global__ __launch_bounds__(256)
void decode_attn_kernel(const float* __restrict__ Kc, const float* __restrict__ Vc,
                        const float* __restrict__ q1, const float* __restrict__ k1,
                        const float* __restrict__ v1, float* __restrict__ out)
{
    __shared__ float qs[HD];
    __shared__ float sc[Sn + 1];
    __shared__ float red[256];
    __shared__ float oacc[2][HD];

    int n = blockIdx.x, b = blockIdx.y;
    int tid = threadIdx.x;
    const float scale = 0.08838834764831845f;

    if (tid < HD) qs[tid] = q1[(size_t)b * NHHD + n * HD + tid];
    __syncthreads();

    // scores over S+1 keys
    for (int t = tid; t <= Sn; t += 256) {
        const float* kp = (t < Sn) ? &Kc[(((size_t)b * Sn + t) * NHn + n) * HD]
                                   : &k1[(size_t)b * NHHD + n * HD];
        float acc = 0.f;
#pragma unroll
        for (int d = 0; d < HD; d += 4) {
            float4 kv = *(const float4*)&kp[d];
            acc += qs[d] * kv.x + qs[d + 1] * kv.y + qs[d + 2] * kv.z + qs[d + 3] * kv.w;
        }
        sc[t] = acc * scale;
    }
    __syncthreads();

    // max reduce
    float mx = -1e30f;
    for (int t = tid; t <= Sn; t += 256) mx = fmaxf(mx, sc[t]);
    red[tid] = mx;
    __syncthreads();
    for (int s = 128; s > 0; s >>= 1) {
        if (tid < s) red[tid] = fmaxf(red[tid], red[tid + s]);
        __syncthreads();
    }
    mx = red[0];
    __syncthreads();

    // exp + sum reduce
    float ls = 0.f;
    for (int t = tid; t <= Sn; t += 256) {
        float p = __expf(sc[t] - mx);
        sc[t] = p;
        ls += p;
    }
    red[tid] = ls;
    __syncthreads();
    for (int s = 128; s > 0; s >>= 1) {
        if (tid < s) red[tid] += red[tid + s];
        __syncthreads();
    }
    float inv = 1.f / red[0];
    __syncthreads();

    // weighted sum of V. 2 groups of 128 threads split the t-range.
    int grp = tid >> 7;       // 0 or 1
    int h   = tid & 127;
    float acc = 0.f;
#pragma unroll 4
    for (int t = grp; t < Sn; t += 2)
        acc += sc[t] * Vc[(((size_t)b * Sn + t) * NHn + n) * HD + h];
    if (grp == 1) acc += sc[Sn] * v1[(size_t)b * NHHD + n * HD + h];
    oacc[grp][h] = acc;
    __syncthreads();
    if (tid < HD)
        out[(size_t)b * NHHD + n * HD + tid] = (oacc[0][tid] + oacc[1][tid]) * inv;
}

// ------------------- launch -------------------
extern "C" void kernel_launch(void* const* d_in, const int* in_sizes, int n_in,
                              void* d_out, int out_size)
{
    (void)in_sizes; (void)n_in; (void)out_size;
    const float* x  = (const float*)d_in[0];
    const float* xn = (const float*)d_in[1];
    const float* wq = (const float*)d_in[2];
    const float* wk = (const float*)d_in[3];
    const float* wv = (const float*)d_in[4];
    const float* wo = (const float*)d_in[5];
    float* out = (float*)d_out;

    float *q, *k, *v, *attn, *q1, *k1, *v1, *qkv1;
    cudaGetSymbolAddress((void**)&q,    g_q);
    cudaGetSymbolAddress((void**)&k,    g_k);
    cudaGetSymbolAddress((void**)&v,    g_v);
    cudaGetSymbolAddress((void**)&attn, g_attn);
    cudaGetSymbolAddress((void**)&q1,   g_q1);
    cudaGetSymbolAddress((void**)&k1,   g_k1);
    cudaGetSymbolAddress((void**)&v1,   g_v1);
    cudaGetSymbolAddress((void**)&qkv1, g_qkv1);

    const int M  = Bz * Sn;    // 4096
    const int Nn = NHHD;       // 2048
    const int Kk = DM;         // 2048

    dim3 gproj(Nn / 64, (M + 63) / 64);     // (32, 64)
    dim3 gdec (Nn / 64, 1);                 // M = 2 -> one row of blocks

    // 1. prefill projections
    gemm64_kernel<false><<<gproj, 256>>>(x, wq, q, M, Nn, Kk);
    gemm64_kernel<false><<<gproj, 256>>>(x, wk, k, M, Nn, Kk);
    gemm64_kernel<false><<<gproj, 256>>>(x, wv, v, M, Nn, Kk);

    // 2. decode projections (M = Bz rows)
    gemm64_kernel<false><<<gdec, 256>>>(xn, wq, q1, Bz, Nn, Kk);
    gemm64_kernel<false><<<gdec, 256>>>(xn, wk, k1, Bz, Nn, Kk);
    gemm64_kernel<false><<<gdec, 256>>>(xn, wv, v1, Bz, Nn, Kk);

    // 3. prefill flash attention
    size_t smem = (size_t)(3 * BQ * HDP + BQ * SP) * sizeof(float);  // 118784 B
    cudaFuncSetAttribute(flash_prefill_kernel,
                         cudaFuncAttributeMaxDynamicSharedMemorySize, (int)smem);
    dim3 gattn(Sn / BQ, NHn, Bz);  // (32,16,2)
    flash_prefill_kernel<<<gattn, 256, smem>>>(q, k, v, attn);

    // 4. decode attention
    dim3 gdatt(NHn, Bz);
    decode_attn_kernel<<<gdatt, 256>>>(k, v, q1, k1, v1, qkv1);

    // 5. output projections (contract over n*h -> NT gemm with wo)
    gemm64_kernel<true><<<gproj, 256>>>(attn, wo, out, M, DM, NHHD);
    gemm64_kernel<true><<<gdec, 256>>>(qkv1, wo, out + (size_t)Bz * Sn * DM, Bz, DM, NHHD);
}

// round 3
// speedup vs baseline: 1.5783x; 1.5783x over previous
#include <cuda_runtime.h>
#include <cstdint>
#include <math.h>

// Problem constants
#define Bz   2
#define Sn   2048
#define DM   2048
#define NHn  16
#define HD   128
#define NHHD 2048   // NHn*HD

// ------------------- scratch (device globals; no allocation) -------------------
__device__ float g_q   [(size_t)Bz*Sn*NHHD];
__device__ float g_k   [(size_t)Bz*Sn*NHHD];
__device__ float g_v   [(size_t)Bz*Sn*NHHD];
__device__ float g_attn[(size_t)Bz*Sn*NHHD];
__device__ float g_q1  [Bz*NHHD];
__device__ float g_k1  [Bz*NHHD];
__device__ float g_v1  [Bz*NHHD];
__device__ float g_qkv1[Bz*NHHD];

// ------------------- tf32 helpers -------------------
__device__ __forceinline__ uint32_t tf32r(float x) {
    uint32_t u;
    asm("cvt.rna.tf32.f32 %0, %1;" : "=r"(u) : "f"(x));
    return u;
}

__device__ __forceinline__ void mma_tf32(float* c, const uint32_t* a, uint32_t b0, uint32_t b1) {
    asm volatile("mma.sync.aligned.m16n8k8.row.col.f32.tf32.tf32.f32 "
                 "{%0,%1,%2,%3}, {%4,%5,%6,%7}, {%8,%9}, {%0,%1,%2,%3};"
                 : "+f"(c[0]), "+f"(c[1]), "+f"(c[2]), "+f"(c[3])
                 : "r"(a[0]), "r"(a[1]), "r"(a[2]), "r"(a[3]), "r"(b0), "r"(b1));
}

__device__ __forceinline__ void cp16(uint32_t dst, const void* src) {
    asm volatile("cp.async.cg.shared.global [%0], [%1], 16;" :: "r"(dst), "l"(src));
}
__device__ __forceinline__ void cp_commit() { asm volatile("cp.async.commit_group;"); }
template<int N> __device__ __forceinline__ void cp_wait() {
    asm volatile("cp.async.wait_group %0;" :: "n"(N));
}

// ------------------- tf32 tensor-core SGEMM -------------------
// C[M,N] = A[M,K] @ B,   B is [K,N] (TRANSB=false) or [N,K] (TRANSB=true, C = A @ B^T)
// Requires M%128==0, N%128==0, K%32==0 (true for all uses here: 4096x2048x2048).
// Block 128x128x32, 256 threads (8 warps as 2x4), warp tile 64x32, mma m16n8k8.
#define AST 36     // As row stride (floats): banks (m*36+k)%32 = (4g+t4) conflict-free
#define BST 136    // Bs row stride (floats): banks (k*136+n)%32 = (8t4+g) conflict-free

template<bool TRANSB>
__global__ __launch_bounds__(256)
void gemm_tf32(const float* __restrict__ A, const float* __restrict__ Bm,
               float* __restrict__ C, int M, int N, int K)
{
    extern __shared__ float sm[];
    float* As = sm;                 // 2 * 128 * AST
    float* Bs = sm + 2 * 128 * AST; // 2 * 32  * BST

    const int tid  = threadIdx.x;
    const int lane = tid & 31;
    const int wid  = tid >> 5;
    const int wm   = wid >> 2;      // 0..1
    const int wn   = wid & 3;       // 0..3
    const int g    = lane >> 2;     // 0..7
    const int t4   = lane & 3;      // 0..3

    const int m0 = blockIdx.y * 128;
    const int n0 = blockIdx.x * 128;

    const uint32_t s_as = (uint32_t)__cvta_generic_to_shared(As);
    const uint32_t s_bs = (uint32_t)__cvta_generic_to_shared(Bs);

    float acc[4][4][4];
#pragma unroll
    for (int i = 0; i < 4; i++)
#pragma unroll
        for (int j = 0; j < 4; j++)
#pragma unroll
            for (int r = 0; r < 4; r++) acc[i][j][r] = 0.f;

    float4 breg[4];  // NT staging pipeline
    const int KT = K / 32;

    // ---- staging helpers (inlined by macros for clarity) ----
#define LOAD_A(buf, k0)                                                          \
    {                                                                            \
        _Pragma("unroll")                                                        \
        for (int it = 0; it < 4; it++) {                                         \
            int idx = tid + it * 256;                                            \
            int mm = idx >> 3;                                                   \
            int k4 = (idx & 7) * 4;                                              \
            cp16(s_as + (((buf) * 128 + mm) * AST + k4) * 4,                     \
                 &A[(size_t)(m0 + mm) * K + (k0) + k4]);                         \
        }                                                                        \
    }
#define LOAD_B_NN(buf, k0)                                                       \
    {                                                                            \
        _Pragma("unroll")                                                        \
        for (int it = 0; it < 4; it++) {                                         \
            int idx = tid + it * 256;                                            \
            int kk = idx >> 5;                                                   \
            int n4 = (idx & 31) * 4;                                             \
            cp16(s_bs + (((buf) * 32 + kk) * BST + n4) * 4,                      \
                 &Bm[(size_t)((k0) + kk) * N + n0 + n4]);                        \
        }                                                                        \
    }
#define LDG_B_NT(k0)                                                             \
    {                                                                            \
        _Pragma("unroll")                                                        \
        for (int it = 0; it < 4; it++) {                                         \
            int idx = tid + it * 256;                                            \
            int nn = idx & 127;                                                  \
            int k4 = (idx >> 7) * 4;                                             \
            breg[it] = *(const float4*)&Bm[(size_t)(n0 + nn) * K + (k0) + k4];   \
        }                                                                        \
    }
#define STS_B_NT(buf)                                                            \
    {                                                                            \
        _Pragma("unroll")                                                        \
        for (int it = 0; it < 4; it++) {                                         \
            int idx = tid + it * 256;                                            \
            int nn = idx & 127;                                                  \
            int k4 = (idx >> 7) * 4;                                             \
            Bs[((buf) * 32 + k4 + 0) * BST + nn] = breg[it].x;                   \
            Bs[((buf) * 32 + k4 + 1) * BST + nn] = breg[it].y;                   \
            Bs[((buf) * 32 + k4 + 2) * BST + nn] = breg[it].z;                   \
            Bs[((buf) * 32 + k4 + 3) * BST + nn] = breg[it].w;                   \
        }                                                                        \
    }

    // ---- prologue ----
    LOAD_A(0, 0);
    if constexpr (!TRANSB) { LOAD_B_NN(0, 0); }
    else                   { LDG_B_NT(0); }
    cp_commit();
    if constexpr (TRANSB)  { STS_B_NT(0); }

    for (int kt = 0; kt < KT; kt++) {
        const int buf  = kt & 1;
        const int nbuf = buf ^ 1;
        const bool has_next = (kt + 1) < KT;

        if (has_next) {
            LOAD_A(nbuf, (kt + 1) * 32);
            if constexpr (!TRANSB) { LOAD_B_NN(nbuf, (kt + 1) * 32); }
            cp_commit();
            if constexpr (TRANSB)  { LDG_B_NT((kt + 1) * 32); }
        }
        if (has_next) cp_wait<1>(); else cp_wait<0>();
        __syncthreads();

        // ---- compute on buf ----
#pragma unroll
        for (int ks = 0; ks < 4; ks++) {
            const int kk = ks * 8;
            uint32_t a[4][4];
#pragma unroll
            for (int i = 0; i < 4; i++) {
                const int rm = wm * 64 + i * 16;
                const float* ap = &As[(buf * 128 + rm + g) * AST + kk + t4];
                a[i][0] = tf32r(ap[0]);
                a[i][1] = tf32r(ap[8 * AST]);
                a[i][2] = tf32r(ap[4]);
                a[i][3] = tf32r(ap[8 * AST + 4]);
            }
#pragma unroll
            for (int j = 0; j < 4; j++) {
                const int cn = wn * 32 + j * 8;
                const float* bp = &Bs[(buf * 32 + kk + t4) * BST + cn + g];
                uint32_t b0 = tf32r(bp[0]);
                uint32_t b1 = tf32r(bp[4 * BST]);
#pragma unroll
                for (int i = 0; i < 4; i++) mma_tf32(acc[i][j], a[i], b0, b1);
            }
        }

        if (TRANSB && has_next) { STS_B_NT(nbuf); }
        __syncthreads();
    }

    // ---- epilogue ----
#pragma unroll
    for (int i = 0; i < 4; i++) {
#pragma unroll
        for (int j = 0; j < 4; j++) {
            const int mrow = m0 + wm * 64 + i * 16 + g;
            const int ccol = n0 + wn * 32 + j * 8 + 2 * t4;
            float2 lo = make_float2(acc[i][j][0], acc[i][j][1]);
            float2 hi = make_float2(acc[i][j][2], acc[i][j][3]);
            *(float2*)&C[(size_t)mrow * N + ccol]       = lo;
            *(float2*)&C[(size_t)(mrow + 8) * N + ccol] = hi;
        }
    }
#undef LOAD_A
#undef LOAD_B_NN
#undef LDG_B_NT
#undef STS_B_NT
}

// ------------------- tiny decode projections (M = Bz = 2) -------------------
// out[b][n] = sum_k xn[b][k] * w[k][n]     (NN, coalesced on w rows)
__global__ __launch_bounds__(256)
void decode_proj_kernel(const float* __restrict__ xn, const float* __restrict__ w,
                        float* __restrict__ out)
{
    __shared__ float xs[DM];
    const int tid = threadIdx.x;
    const int b = blockIdx.y;
    const int n = blockIdx.x * 256 + tid;
    for (int k = tid; k < DM; k += 256) xs[k] = xn[(size_t)b * DM + k];
    __syncthreads();
    float acc = 0.f;
#pragma unroll 8
    for (int k = 0; k < DM; k++) acc += xs[k] * w[(size_t)k * NHHD + n];
    out[(size_t)b * NHHD + n] = acc;
}

// out1[b][d] = sum_nh qkv1[b][nh] * wo[d][nh]   (warp per output d, coalesced wo rows)
__global__ __launch_bounds__(256)
void decode_outproj_kernel(const float* __restrict__ qkv1, const float* __restrict__ wo,
                           float* __restrict__ out)
{
    __shared__ float qs[NHHD];
    const int tid = threadIdx.x;
    const int lane = tid & 31, wid = tid >> 5;
    const int b = blockIdx.y;
    const int d = blockIdx.x * 8 + wid;
    for (int k = tid; k < NHHD; k += 256) qs[k] = qkv1[(size_t)b * NHHD + k];
    __syncthreads();
    float acc = 0.f;
#pragma unroll
    for (int nh = lane * 4; nh < NHHD; nh += 128) {
        float4 wv = *(const float4*)&wo[(size_t)d * NHHD + nh];
        acc += qs[nh] * wv.x + qs[nh + 1] * wv.y + qs[nh + 2] * wv.z + qs[nh + 3] * wv.w;
    }
#pragma unroll
    for (int s = 16; s; s >>= 1) acc += __shfl_xor_sync(0xffffffffu, acc, s);
    if (lane == 0) out[(size_t)b * DM + d] = acc;
}

// ------------------- flash attention prefill (causal) -------------------
#define BQ  64
#define HDP 132
#define SP  68

__global__ __launch_bounds__(256)
void flash_prefill_kernel(const float* __restrict__ Q, const float* __restrict__ Kc,
                          const float* __restrict__ Vc, float* __restrict__ O)
{
    extern __shared__ float sm[];
    float* Qs = sm;
    float* Ks = Qs + BQ * HDP;
    float* Vs = Ks + BQ * HDP;
    float* Ss = Vs + BQ * HDP;

    int tid = threadIdx.x;
    int qt = blockIdx.x, n = blockIdx.y, b = blockIdx.z;
    int q0 = qt * BQ;
    const float scale = 0.08838834764831845f;

#pragma unroll
    for (int it = 0; it < 8; it++) {
        int idx = tid + it * 256;
        int r  = idx >> 5;
        int c4 = (idx & 31) * 4;
        float4 v = *(const float4*)&Q[(((size_t)b * Sn + q0 + r) * NHn + n) * HD + c4];
        *(float4*)&Qs[r * HDP + c4] = v;
    }

    int r  = tid >> 2;
    int cg = tid & 3;

    float o[32];
#pragma unroll
    for (int i = 0; i < 32; i++) o[i] = 0.f;
    float m = -1e30f, l = 0.f;

    for (int kt = 0; kt <= qt; kt++) {
        int k0 = kt * BQ;
        __syncthreads();
#pragma unroll
        for (int it = 0; it < 8; it++) {
            int idx = tid + it * 256;
            int rr = idx >> 5;
            int c4 = (idx & 31) * 4;
            size_t gofs = (((size_t)b * Sn + k0 + rr) * NHn + n) * HD + c4;
            *(float4*)&Ks[rr * HDP + c4] = *(const float4*)&Kc[gofs];
            *(float4*)&Vs[rr * HDP + c4] = *(const float4*)&Vc[gofs];
        }
        __syncthreads();

        float sv[16];
#pragma unroll
        for (int jj = 0; jj < 16; jj++) sv[jj] = 0.f;
        for (int d = 0; d < HD; d += 4) {
            float4 qv = *(const float4*)&Qs[r * HDP + d];
#pragma unroll
            for (int jj = 0; jj < 16; jj++) {
                int j = cg + 4 * jj;
                float4 kv = *(const float4*)&Ks[j * HDP + d];
                sv[jj] += qv.x * kv.x + qv.y * kv.y + qv.z * kv.z + qv.w * kv.w;
            }
        }

#pragma unroll
        for (int jj = 0; jj < 16; jj++) {
            int j = cg + 4 * jj;
            bool valid = (k0 + j) <= (q0 + r);
            sv[jj] = valid ? sv[jj] * scale : -1e30f;
        }

        float tmax = sv[0];
#pragma unroll
        for (int jj = 1; jj < 16; jj++) tmax = fmaxf(tmax, sv[jj]);
        tmax = fmaxf(tmax, __shfl_xor_sync(0xffffffffu, tmax, 1));
        tmax = fmaxf(tmax, __shfl_xor_sync(0xffffffffu, tmax, 2));
        float mnew = fmaxf(m, tmax);

        float lsum = 0.f;
#pragma unroll
        for (int jj = 0; jj < 16; jj++) {
            float p = __expf(sv[jj] - mnew);
            sv[jj] = p;
            lsum += p;
        }
        lsum += __shfl_xor_sync(0xffffffffu, lsum, 1);
        lsum += __shfl_xor_sync(0xffffffffu, lsum, 2);

        float alpha = __expf(m - mnew);
        m = mnew;
        l = l * alpha + lsum;
#pragma unroll
        for (int i = 0; i < 32; i++) o[i] *= alpha;

#pragma unroll
        for (int jj = 0; jj < 16; jj++) Ss[r * SP + cg + 4 * jj] = sv[jj];
        __syncwarp();

#pragma unroll 4
        for (int j = 0; j < BQ; j++) {
            float p = Ss[r * SP + j];
#pragma unroll
            for (int cc = 0; cc < 8; cc++) {
                float4 vv = *(const float4*)&Vs[j * HDP + (cg + 4 * cc) * 4];
                o[cc * 4 + 0] += p * vv.x;
                o[cc * 4 + 1] += p * vv.y;
                o[cc * 4 + 2] += p * vv.z;
                o[cc * 4 + 3] += p * vv.w;
            }
        }
    }

    float inv = 1.f / l;
    size_t obase = (((size_t)b * Sn + q0 + r) * NHn + n) * HD;
#pragma unroll
    for (int cc = 0; cc < 8; cc++) {
        float4 ov = make_float4(o[cc * 4 + 0] * inv, o[cc * 4 + 1] * inv,
                                o[cc * 4 + 2] * inv, o[cc * 4 + 3] * inv);
        *(float4*)&O[obase + (size_t)(cg + 4 * cc) * 4] = ov;
    }
}

// ------------------- decode attention -------------------
__global__ __launch_bounds__(256)
void decode_attn_kernel(const float* __restrict__ Kc, const float* __restrict__ Vc,
                        const float* __restrict__ q1, const float* __restrict__ k1,
                        const float* __restrict__ v1, float* __restrict__ out)
{
    __shared__ float qs[HD];
    __shared__ float sc[Sn + 1];
    __shared__ float red[256];
    __shared__ float oacc[2][HD];

    int n = blockIdx.x, b = blockIdx.y;
    int tid = threadIdx.x;
    const float scale = 0.08838834764831845f;

    if (tid < HD) qs[tid] = q1[(size_t)b * NHHD + n * HD + tid];
    __syncthreads();

    for (int t = tid; t <= Sn; t += 256) {
        const float* kp = (t < Sn) ? &Kc[(((size_t)b * Sn + t) * NHn + n) * HD]
                                   : &k1[(size_t)b * NHHD + n * HD];
        float acc = 0.f;
#pragma unroll
        for (int d = 0; d < HD; d += 4) {
            float4 kv = *(const float4*)&kp[d];
            acc += qs[d] * kv.x + qs[d + 1] * kv.y + qs[d + 2] * kv.z + qs[d + 3] * kv.w;
        }
        sc[t] = acc * scale;
    }
    __syncthreads();

    float mx = -1e30f;
    for (int t = tid; t <= Sn; t += 256) mx = fmaxf(mx, sc[t]);
    red[tid] = mx;
    __syncthreads();
    for (int s = 128; s > 0; s >>= 1) {
        if (tid < s) red[tid] = fmaxf(red[tid], red[tid + s]);
        __syncthreads();
    }
    mx = red[0];
    __syncthreads();

    float ls = 0.f;
    for (int t = tid; t <= Sn; t += 256) {
        float p = __expf(sc[t] - mx);
        sc[t] = p;
        ls += p;
    }
    red[tid] = ls;
    __syncthreads();
    for (int s = 128; s > 0; s >>= 1) {
        if (tid < s) red[tid] += red[tid + s];
        __syncthreads();
    }
    float inv = 1.f / red[0];
    __syncthreads();

    int grp = tid >> 7;
    int h   = tid & 127;
    float acc = 0.f;
#pragma unroll 4
    for (int t = grp; t < Sn; t += 2)
        acc += sc[t] * Vc[(((size_t)b * Sn + t) * NHn + n) * HD + h];
    if (grp == 1) acc += sc[Sn] * v1[(size_t)b * NHHD + n * HD + h];
    oacc[grp][h] = acc;
    __syncthreads();
    if (tid < HD)
        out[(size_t)b * NHHD + n * HD + tid] = (oacc[0][tid] + oacc[1][tid]) * inv;
}

// ------------------- launch -------------------
extern "C" void kernel_launch(void* const* d_in, const int* in_sizes, int n_in,
                              void* d_out, int out_size)
{
    (void)in_sizes; (void)n_in; (void)out_size;
    const float* x  = (const float*)d_in[0];
    const float* xn = (const float*)d_in[1];
    const float* wq = (const float*)d_in[2];
    const float* wk = (const float*)d_in[3];
    const float* wv = (const float*)d_in[4];
    const float* wo = (const float*)d_in[5];
    float* out = (float*)d_out;

    float *q, *k, *v, *attn, *q1, *k1, *v1, *qkv1;
    cudaGetSymbolAddress((void**)&q,    g_q);
    cudaGetSymbolAddress((void**)&k,    g_k);
    cudaGetSymbolAddress((void**)&v,    g_v);
    cudaGetSymbolAddress((void**)&attn, g_attn);
    cudaGetSymbolAddress((void**)&q1,   g_q1);
    cudaGetSymbolAddress((void**)&k1,   g_k1);
    cudaGetSymbolAddress((void**)&v1,   g_v1);
    cudaGetSymbolAddress((void**)&qkv1, g_qkv1);

    const int M  = Bz * Sn;    // 4096
    const int Nn = NHHD;       // 2048
    const int Kk = DM;         // 2048

    // tf32 GEMM smem: double-buffered A(128xAST) + B(32xBST)
    const int gsmem = (2 * 128 * AST + 2 * 32 * BST) * (int)sizeof(float);  // 71680
    cudaFuncSetAttribute(gemm_tf32<false>,
                         cudaFuncAttributeMaxDynamicSharedMemorySize, gsmem);
    cudaFuncSetAttribute(gemm_tf32<true>,
                         cudaFuncAttributeMaxDynamicSharedMemorySize, gsmem);

    dim3 gproj(Nn / 128, M / 128);  // (16, 32)

    // 1. prefill projections (tf32 tensor cores)
    gemm_tf32<false><<<gproj, 256, gsmem>>>(x, wq, q, M, Nn, Kk);
    gemm_tf32<false><<<gproj, 256, gsmem>>>(x, wk, k, M, Nn, Kk);
    gemm_tf32<false><<<gproj, 256, gsmem>>>(x, wv, v, M, Nn, Kk);

    // 2. decode projections (skinny, memory-bound)
    dim3 gdp(NHHD / 256, Bz);
    decode_proj_kernel<<<gdp, 256>>>(xn, wq, q1);
    decode_proj_kernel<<<gdp, 256>>>(xn, wk, k1);
    decode_proj_kernel<<<gdp, 256>>>(xn, wv, v1);

    // 3. prefill flash attention
    size_t smem = (size_t)(3 * BQ * HDP + BQ * SP) * sizeof(float);
    cudaFuncSetAttribute(flash_prefill_kernel,
                         cudaFuncAttributeMaxDynamicSharedMemorySize, (int)smem);
    dim3 gattn(Sn / BQ, NHn, Bz);
    flash_prefill_kernel<<<gattn, 256, smem>>>(q, k, v, attn);

    // 4. decode attention
    dim3 gdatt(NHn, Bz);
    decode_attn_kernel<<<gdatt, 256>>>(k, v, q1, k1, v1, qkv1);

    // 5. output projections
    gemm_tf32<true><<<gproj, 256, gsmem>>>(attn, wo, out, M, DM, NHHD);
    dim3 gdo(DM / 8, Bz);
    decode_outproj_kernel<<<gdo, 256>>>(qkv1, wo, out + (size_t)Bz * Sn * DM);
}

// round 4
// speedup vs baseline: 3.5461x; 2.2468x over previous
#include <cuda_runtime.h>
#include <cstdint>
#include <math.h>

// Problem constants
#define Bz   2
#define Sn   2048
#define DM   2048
#define NHn  16
#define HD   128
#define NHHD 2048   // NHn*HD

// ------------------- scratch (device globals; no allocation) -------------------
__device__ float g_q   [(size_t)Bz*Sn*NHHD];
__device__ float g_k   [(size_t)Bz*Sn*NHHD];
__device__ float g_v   [(size_t)Bz*Sn*NHHD];
__device__ float g_attn[(size_t)Bz*Sn*NHHD];
__device__ float g_q1  [Bz*NHHD];
__device__ float g_k1  [Bz*NHHD];
__device__ float g_v1  [Bz*NHHD];
__device__ float g_qkv1[Bz*NHHD];

// ------------------- tf32 helpers -------------------
__device__ __forceinline__ uint32_t tf32r(float x) {
    uint32_t u;
    asm("cvt.rna.tf32.f32 %0, %1;" : "=r"(u) : "f"(x));
    return u;
}

__device__ __forceinline__ void mma_tf32(float* c, const uint32_t* a, uint32_t b0, uint32_t b1) {
    asm volatile("mma.sync.aligned.m16n8k8.row.col.f32.tf32.tf32.f32 "
                 "{%0,%1,%2,%3}, {%4,%5,%6,%7}, {%8,%9}, {%0,%1,%2,%3};"
                 : "+f"(c[0]), "+f"(c[1]), "+f"(c[2]), "+f"(c[3])
                 : "r"(a[0]), "r"(a[1]), "r"(a[2]), "r"(a[3]), "r"(b0), "r"(b1));
}

__device__ __forceinline__ void cp16(uint32_t dst, const void* src) {
    asm volatile("cp.async.cg.shared.global [%0], [%1], 16;" :: "r"(dst), "l"(src));
}
__device__ __forceinline__ void cp_commit() { asm volatile("cp.async.commit_group;"); }
template<int N> __device__ __forceinline__ void cp_wait() {
    asm volatile("cp.async.wait_group %0;" :: "n"(N));
}

// ------------------- tf32 tensor-core SGEMM (unchanged from R3) -------------------
#define AST 36
#define BST 136

template<bool TRANSB>
__global__ __launch_bounds__(256)
void gemm_tf32(const float* __restrict__ A, const float* __restrict__ Bm,
               float* __restrict__ C, int M, int N, int K)
{
    extern __shared__ float sm[];
    float* As = sm;
    float* Bs = sm + 2 * 128 * AST;

    const int tid  = threadIdx.x;
    const int lane = tid & 31;
    const int wid  = tid >> 5;
    const int wm   = wid >> 2;
    const int wn   = wid & 3;
    const int g    = lane >> 2;
    const int t4   = lane & 3;

    const int m0 = blockIdx.y * 128;
    const int n0 = blockIdx.x * 128;

    const uint32_t s_as = (uint32_t)__cvta_generic_to_shared(As);
    const uint32_t s_bs = (uint32_t)__cvta_generic_to_shared(Bs);

    float acc[4][4][4];
#pragma unroll
    for (int i = 0; i < 4; i++)
#pragma unroll
        for (int j = 0; j < 4; j++)
#pragma unroll
            for (int r = 0; r < 4; r++) acc[i][j][r] = 0.f;

    float4 breg[4];
    const int KT = K / 32;

#define LOAD_A(buf, k0)                                                          \
    {                                                                            \
        _Pragma("unroll")                                                        \
        for (int it = 0; it < 4; it++) {                                         \
            int idx = tid + it * 256;                                            \
            int mm = idx >> 3;                                                   \
            int k4 = (idx & 7) * 4;                                              \
            cp16(s_as + (((buf) * 128 + mm) * AST + k4) * 4,                     \
                 &A[(size_t)(m0 + mm) * K + (k0) + k4]);                         \
        }                                                                        \
    }
#define LOAD_B_NN(buf, k0)                                                       \
    {                                                                            \
        _Pragma("unroll")                                                        \
        for (int it = 0; it < 4; it++) {                                         \
            int idx = tid + it * 256;                                            \
            int kk = idx >> 5;                                                   \
            int n4 = (idx & 31) * 4;                                             \
            cp16(s_bs + (((buf) * 32 + kk) * BST + n4) * 4,                      \
                 &Bm[(size_t)((k0) + kk) * N + n0 + n4]);                        \
        }                                                                        \
    }
#define LDG_B_NT(k0)                                                             \
    {                                                                            \
        _Pragma("unroll")                                                        \
        for (int it = 0; it < 4; it++) {                                         \
            int idx = tid + it * 256;                                            \
            int nn = idx & 127;                                                  \
            int k4 = (idx >> 7) * 4;                                             \
            breg[it] = *(const float4*)&Bm[(size_t)(n0 + nn) * K + (k0) + k4];   \
        }                                                                        \
    }
#define STS_B_NT(buf)                                                            \
    {                                                                            \
        _Pragma("unroll")                                                        \
        for (int it = 0; it < 4; it++) {                                         \
            int idx = tid + it * 256;                                            \
            int nn = idx & 127;                                                  \
            int k4 = (idx >> 7) * 4;                                             \
            Bs[((buf) * 32 + k4 + 0) * BST + nn] = breg[it].x;                   \
            Bs[((buf) * 32 + k4 + 1) * BST + nn] = breg[it].y;                   \
            Bs[((buf) * 32 + k4 + 2) * BST + nn] = breg[it].z;                   \
            Bs[((buf) * 32 + k4 + 3) * BST + nn] = breg[it].w;                   \
        }                                                                        \
    }

    LOAD_A(0, 0);
    if constexpr (!TRANSB) { LOAD_B_NN(0, 0); }
    else                   { LDG_B_NT(0); }
    cp_commit();
    if constexpr (TRANSB)  { STS_B_NT(0); }

    for (int kt = 0; kt < KT; kt++) {
        const int buf  = kt & 1;
        const int nbuf = buf ^ 1;
        const bool has_next = (kt + 1) < KT;

        if (has_next) {
            LOAD_A(nbuf, (kt + 1) * 32);
            if constexpr (!TRANSB) { LOAD_B_NN(nbuf, (kt + 1) * 32); }
            cp_commit();
            if constexpr (TRANSB)  { LDG_B_NT((kt + 1) * 32); }
        }
        if (has_next) cp_wait<1>(); else cp_wait<0>();
        __syncthreads();

#pragma unroll
        for (int ks = 0; ks < 4; ks++) {
            const int kk = ks * 8;
            uint32_t a[4][4];
#pragma unroll
            for (int i = 0; i < 4; i++) {
                const int rm = wm * 64 + i * 16;
                const float* ap = &As[(buf * 128 + rm + g) * AST + kk + t4];
                a[i][0] = tf32r(ap[0]);
                a[i][1] = tf32r(ap[8 * AST]);
                a[i][2] = tf32r(ap[4]);
                a[i][3] = tf32r(ap[8 * AST + 4]);
            }
#pragma unroll
            for (int j = 0; j < 4; j++) {
                const int cn = wn * 32 + j * 8;
                const float* bp = &Bs[(buf * 32 + kk + t4) * BST + cn + g];
                uint32_t b0 = tf32r(bp[0]);
                uint32_t b1 = tf32r(bp[4 * BST]);
#pragma unroll
                for (int i = 0; i < 4; i++) mma_tf32(acc[i][j], a[i], b0, b1);
            }
        }

        if (TRANSB && has_next) { STS_B_NT(nbuf); }
        __syncthreads();
    }

#pragma unroll
    for (int i = 0; i < 4; i++) {
#pragma unroll
        for (int j = 0; j < 4; j++) {
            const int mrow = m0 + wm * 64 + i * 16 + g;
            const int ccol = n0 + wn * 32 + j * 8 + 2 * t4;
            float2 lo = make_float2(acc[i][j][0], acc[i][j][1]);
            float2 hi = make_float2(acc[i][j][2], acc[i][j][3]);
            *(float2*)&C[(size_t)mrow * N + ccol]       = lo;
            *(float2*)&C[(size_t)(mrow + 8) * N + ccol] = hi;
        }
    }
#undef LOAD_A
#undef LOAD_B_NN
#undef LDG_B_NT
#undef STS_B_NT
}

// ------------------- tensor-core flash attention prefill (causal) -------------------
// Q,K,V fp32 [B,S,NH,HD]. Block = (q-tile of 128, head, batch), 256 threads / 8 warps.
// Each warp owns 16 full query rows -> softmax row stats are intra-quad shuffles only.
// Smem tiles pre-converted to tf32 bits; strides chosen conflict-free for fragments.
#define FQ   128         // q rows per block
#define FK   64          // kv rows per tile
#define QST  132         // Qs/Ks stride (4 mod 32 -> banks 4g+t4)
#define VST  136         // Vs stride   (8 mod 32 -> banks 8t4+g)
#define PST  68          // Ps stride   (4 mod 32)

__global__ __launch_bounds__(256)
void flash_tc_kernel(const float* __restrict__ Q, const float* __restrict__ K,
                     const float* __restrict__ V, float* __restrict__ O)
{
    extern __shared__ uint32_t smu[];
    uint32_t* Qs = smu;                    // FQ * QST
    uint32_t* Ks = Qs + FQ * QST;          // FK * QST
    uint32_t* Vs = Ks + FK * QST;          // FK * VST
    uint32_t* Ps = Vs + FK * VST;          // FQ * PST

    const int tid  = threadIdx.x;
    const int lane = tid & 31;
    const int wid  = tid >> 5;
    const int g    = lane >> 2;
    const int t4   = lane & 3;
    const int rm   = wid * 16;

    const int qt = (int)gridDim.x - 1 - (int)blockIdx.x;  // heavy blocks first
    const int n  = blockIdx.y, b = blockIdx.z;
    const int q0 = qt * FQ;

    const float sc2 = 0.08838834764831845f * 1.4426950408889634f;  // scale*log2(e)

    // load Q tile (fp32 -> tf32 bits)
#pragma unroll
    for (int it = 0; it < 16; it++) {
        int idx = tid + it * 256;
        int r  = idx >> 5;
        int c4 = (idx & 31) * 4;
        float4 v = *(const float4*)&Q[(((size_t)b * Sn + q0 + r) * NHn + n) * HD + c4];
        uint32_t* d = &Qs[r * QST + c4];
        d[0] = tf32r(v.x); d[1] = tf32r(v.y); d[2] = tf32r(v.z); d[3] = tf32r(v.w);
    }

    float o[16][4];
#pragma unroll
    for (int j = 0; j < 16; j++)
#pragma unroll
        for (int c = 0; c < 4; c++) o[j][c] = 0.f;
    float m0 = -1e30f, m1 = -1e30f, l0 = 0.f, l1 = 0.f;

    const int ktn = 2 * qt + 2;
    for (int kt = 0; kt < ktn; kt++) {
        const int k0 = kt * FK;
        __syncthreads();
        // load K/V tiles (fp32 -> tf32 bits)
#pragma unroll
        for (int it = 0; it < 8; it++) {
            int idx = tid + it * 256;
            int rr = idx >> 5;
            int c4 = (idx & 31) * 4;
            size_t gofs = (((size_t)b * Sn + k0 + rr) * NHn + n) * HD + c4;
            float4 kv = *(const float4*)&K[gofs];
            float4 vv = *(const float4*)&V[gofs];
            uint32_t* dk = &Ks[rr * QST + c4];
            dk[0] = tf32r(kv.x); dk[1] = tf32r(kv.y); dk[2] = tf32r(kv.z); dk[3] = tf32r(kv.w);
            uint32_t* dv = &Vs[rr * VST + c4];
            dv[0] = tf32r(vv.x); dv[1] = tf32r(vv.y); dv[2] = tf32r(vv.z); dv[3] = tf32r(vv.w);
        }
        __syncthreads();

        // ---- S = Q K^T  (warp: 16 rows x 64 cols) ----
        float s[8][4];
#pragma unroll
        for (int j = 0; j < 8; j++)
#pragma unroll
            for (int c = 0; c < 4; c++) s[j][c] = 0.f;

#pragma unroll
        for (int k8 = 0; k8 < 16; k8++) {
            const int kk = k8 * 8;
            uint32_t a[4];
            a[0] = Qs[(rm + g) * QST + kk + t4];
            a[1] = Qs[(rm + 8 + g) * QST + kk + t4];
            a[2] = Qs[(rm + g) * QST + kk + t4 + 4];
            a[3] = Qs[(rm + 8 + g) * QST + kk + t4 + 4];
#pragma unroll
            for (int j = 0; j < 8; j++) {
                const int cn = j * 8;
                uint32_t b0 = Ks[(cn + g) * QST + kk + t4];
                uint32_t b1 = Ks[(cn + g) * QST + kk + t4 + 4];
                mma_tf32(s[j], a, b0, b1);
            }
        }

        // ---- causal mask (only diagonal tiles) ----
        if (kt >= 2 * qt) {
            const int row0 = q0 + rm + g;
#pragma unroll
            for (int j = 0; j < 8; j++) {
                const int col = k0 + j * 8 + 2 * t4;
                if (col     > row0)     s[j][0] = -1e30f;
                if (col + 1 > row0)     s[j][1] = -1e30f;
                if (col     > row0 + 8) s[j][2] = -1e30f;
                if (col + 1 > row0 + 8) s[j][3] = -1e30f;
            }
        }

        // ---- online softmax (rows g and g+8; quad shuffles) ----
        float r0 = -1e30f, r1 = -1e30f;
#pragma unroll
        for (int j = 0; j < 8; j++) {
            r0 = fmaxf(r0, fmaxf(s[j][0], s[j][1]));
            r1 = fmaxf(r1, fmaxf(s[j][2], s[j][3]));
        }
        r0 = fmaxf(r0, __shfl_xor_sync(0xffffffffu, r0, 1));
        r0 = fmaxf(r0, __shfl_xor_sync(0xffffffffu, r0, 2));
        r1 = fmaxf(r1, __shfl_xor_sync(0xffffffffu, r1, 1));
        r1 = fmaxf(r1, __shfl_xor_sync(0xffffffffu, r1, 2));

        float mn0 = fmaxf(m0, r0), mn1 = fmaxf(m1, r1);
        float al0 = exp2f((m0 - mn0) * sc2), al1 = exp2f((m1 - mn1) * sc2);
        m0 = mn0; m1 = mn1;

#pragma unroll
        for (int j = 0; j < 16; j++) {
            o[j][0] *= al0; o[j][1] *= al0;
            o[j][2] *= al1; o[j][3] *= al1;
        }

        float ls0 = 0.f, ls1 = 0.f;
#pragma unroll
        for (int j = 0; j < 8; j++) {
            float p0 = exp2f((s[j][0] - m0) * sc2);
            float p1 = exp2f((s[j][1] - m0) * sc2);
            float p2 = exp2f((s[j][2] - m1) * sc2);
            float p3 = exp2f((s[j][3] - m1) * sc2);
            ls0 += p0 + p1; ls1 += p2 + p3;
            const int cn = j * 8 + 2 * t4;
            uint2 lo = make_uint2(tf32r(p0), tf32r(p1));
            uint2 hi = make_uint2(tf32r(p2), tf32r(p3));
            *(uint2*)&Ps[(rm + g) * PST + cn]     = lo;
            *(uint2*)&Ps[(rm + 8 + g) * PST + cn] = hi;
        }
        ls0 += __shfl_xor_sync(0xffffffffu, ls0, 1);
        ls0 += __shfl_xor_sync(0xffffffffu, ls0, 2);
        ls1 += __shfl_xor_sync(0xffffffffu, ls1, 1);
        ls1 += __shfl_xor_sync(0xffffffffu, ls1, 2);
        l0 = l0 * al0 + ls0;
        l1 = l1 * al1 + ls1;

        __syncwarp();  // P rows are warp-private; quad cross-reads only

        // ---- O += P V  (warp: 16 rows x 128 cols) ----
#pragma unroll
        for (int k8 = 0; k8 < 8; k8++) {
            const int kk = k8 * 8;
            uint32_t a[4];
            a[0] = Ps[(rm + g) * PST + kk + t4];
            a[1] = Ps[(rm + 8 + g) * PST + kk + t4];
            a[2] = Ps[(rm + g) * PST + kk + t4 + 4];
            a[3] = Ps[(rm + 8 + g) * PST + kk + t4 + 4];
#pragma unroll
            for (int j = 0; j < 16; j++) {
                const int cn = j * 8;
                uint32_t b0 = Vs[(kk + t4) * VST + cn + g];
                uint32_t b1 = Vs[(kk + t4 + 4) * VST + cn + g];
                mma_tf32(o[j], a, b0, b1);
            }
        }
    }

    // ---- epilogue ----
    const float i0 = 1.f / l0, i1 = 1.f / l1;
    const int row0 = q0 + rm + g;
#pragma unroll
    for (int j = 0; j < 16; j++) {
        const int col = j * 8 + 2 * t4;
        *(float2*)&O[(((size_t)b * Sn + row0) * NHn + n) * HD + col] =
            make_float2(o[j][0] * i0, o[j][1] * i0);
        *(float2*)&O[(((size_t)b * Sn + row0 + 8) * NHn + n) * HD + col] =
            make_float2(o[j][2] * i1, o[j][3] * i1);
    }
}

// ------------------- decode projections (fused, k-split, atomic) -------------------
__global__ void decode_zero_kernel(float* q1, float* k1, float* v1)
{
    int i = blockIdx.x * 256 + threadIdx.x;
    if (i < Bz * NHHD) { q1[i] = 0.f; k1[i] = 0.f; v1[i] = 0.f; }
}

// grid (NHHD/256, KSPLIT=16, 3). Each block: 128 k-rows x 256 n-cols of one weight.
__global__ __launch_bounds__(256)
void decode_proj_kernel(const float* __restrict__ xn,
                        const float* __restrict__ wq, const float* __restrict__ wk,
                        const float* __restrict__ wv,
                        float* __restrict__ q1, float* __restrict__ k1,
                        float* __restrict__ v1)
{
    __shared__ float xs[2][128];
    const int tid = threadIdx.x;
    const int pz = blockIdx.z;
    const float* w = (pz == 0) ? wq : (pz == 1) ? wk : wv;
    float* out     = (pz == 0) ? q1 : (pz == 1) ? k1 : v1;

    const int k0 = blockIdx.y * 128;
    const int nn = blockIdx.x * 256 + tid;

    { int bb = tid >> 7, kk = tid & 127; xs[bb][kk] = xn[(size_t)bb * DM + k0 + kk]; }
    __syncthreads();

    float a0 = 0.f, a1 = 0.f;
#pragma unroll 8
    for (int kk = 0; kk < 128; kk++) {
        float wv_ = w[(size_t)(k0 + kk) * NHHD + nn];
        a0 += xs[0][kk] * wv_;
        a1 += xs[1][kk] * wv_;
    }
    atomicAdd(&out[nn], a0);
    atomicAdd(&out[NHHD + nn], a1);
}

// out1[b][d] = sum_nh qkv1[b][nh] * wo[d][nh]; both b in one pass over wo.
__global__ __launch_bounds__(256)
void decode_outproj_kernel(const float* __restrict__ qkv1, const float* __restrict__ wo,
                           float* __restrict__ out)
{
    __shared__ float qs[2][NHHD];
    const int tid = threadIdx.x;
    const int lane = tid & 31, wid = tid >> 5;
    const int d = blockIdx.x * 8 + wid;
    for (int i = tid; i < 2 * NHHD; i += 256)
        qs[i >> 11][i & (NHHD - 1)] = qkv1[i];
    __syncthreads();
    float a0 = 0.f, a1 = 0.f;
#pragma unroll
    for (int nh = lane * 4; nh < NHHD; nh += 128) {
        float4 wv = *(const float4*)&wo[(size_t)d * NHHD + nh];
        a0 += qs[0][nh] * wv.x + qs[0][nh + 1] * wv.y + qs[0][nh + 2] * wv.z + qs[0][nh + 3] * wv.w;
        a1 += qs[1][nh] * wv.x + qs[1][nh + 1] * wv.y + qs[1][nh + 2] * wv.z + qs[1][nh + 3] * wv.w;
    }
#pragma unroll
    for (int s = 16; s; s >>= 1) {
        a0 += __shfl_xor_sync(0xffffffffu, a0, s);
        a1 += __shfl_xor_sync(0xffffffffu, a1, s);
    }
    if (lane == 0) {
        out[d]      = a0;
        out[DM + d] = a1;
    }
}

// ------------------- decode attention (unchanged) -------------------
__global__ __launch_bounds__(256)
void decode_attn_kernel(const float* __restrict__ Kc, const float* __restrict__ Vc,
                        const float* __restrict__ q1, const float* __restrict__ k1,
                        const float* __restrict__ v1, float* __restrict__ out)
{
    __shared__ float qs[HD];
    __shared__ float sc[Sn + 1];
    __shared__ float red[256];
    __shared__ float oacc[2][HD];

    int n = blockIdx.x, b = blockIdx.y;
    int tid = threadIdx.x;
    const float scale = 0.08838834764831845f;

    if (tid < HD) qs[tid] = q1[(size_t)b * NHHD + n * HD + tid];
    __syncthreads();

    for (int t = tid; t <= Sn; t += 256) {
        const float* kp = (t < Sn) ? &Kc[(((size_t)b * Sn + t) * NHn + n) * HD]
                                   : &k1[(size_t)b * NHHD + n * HD];
        float acc = 0.f;
#pragma unroll
        for (int d = 0; d < HD; d += 4) {
            float4 kv = *(const float4*)&kp[d];
            acc += qs[d] * kv.x + qs[d + 1] * kv.y + qs[d + 2] * kv.z + qs[d + 3] * kv.w;
        }
        sc[t] = acc * scale;
    }
    __syncthreads();

    float mx = -1e30f;
    for (int t = tid; t <= Sn; t += 256) mx = fmaxf(mx, sc[t]);
    red[tid] = mx;
    __syncthreads();
    for (int s = 128; s > 0; s >>= 1) {
        if (tid < s) red[tid] = fmaxf(red[tid], red[tid + s]);
        __syncthreads();
    }
    mx = red[0];
    __syncthreads();

    float ls = 0.f;
    for (int t = tid; t <= Sn; t += 256) {
        float p = __expf(sc[t] - mx);
        sc[t] = p;
        ls += p;
    }
    red[tid] = ls;
    __syncthreads();
    for (int s = 128; s > 0; s >>= 1) {
        if (tid < s) red[tid] += red[tid + s];
        __syncthreads();
    }
    float inv = 1.f / red[0];
    __syncthreads();

    int grp = tid >> 7;
    int h   = tid & 127;
    float acc = 0.f;
#pragma unroll 4
    for (int t = grp; t < Sn; t += 2)
        acc += sc[t] * Vc[(((size_t)b * Sn + t) * NHn + n) * HD + h];
    if (grp == 1) acc += sc[Sn] * v1[(size_t)b * NHHD + n * HD + h];
    oacc[grp][h] = acc;
    __syncthreads();
    if (tid < HD)
        out[(size_t)b * NHHD + n * HD + tid] = (oacc[0][tid] + oacc[1][tid]) * inv;
}

// ------------------- launch -------------------
extern "C" void kernel_launch(void* const* d_in, const int* in_sizes, int n_in,
                              void* d_out, int out_size)
{
    (void)in_sizes; (void)n_in; (void)out_size;
    const float* x  = (const float*)d_in[0];
    const float* xn = (const float*)d_in[1];
    const float* wq = (const float*)d_in[2];
    const float* wk = (const float*)d_in[3];
    const float* wv = (const float*)d_in[4];
    const float* wo = (const float*)d_in[5];
    float* out = (float*)d_out;

    float *q, *k, *v, *attn, *q1, *k1, *v1, *qkv1;
    cudaGetSymbolAddress((void**)&q,    g_q);
    cudaGetSymbolAddress((void**)&k,    g_k);
    cudaGetSymbolAddress((void**)&v,    g_v);
    cudaGetSymbolAddress((void**)&attn, g_attn);
    cudaGetSymbolAddress((void**)&q1,   g_q1);
    cudaGetSymbolAddress((void**)&k1,   g_k1);
    cudaGetSymbolAddress((void**)&v1,   g_v1);
    cudaGetSymbolAddress((void**)&qkv1, g_qkv1);

    const int M  = Bz * Sn;    // 4096
    const int Nn = NHHD;       // 2048
    const int Kk = DM;         // 2048

    const int gsmem = (2 * 128 * AST + 2 * 32 * BST) * (int)sizeof(float);
    cudaFuncSetAttribute(gemm_tf32<false>,
                         cudaFuncAttributeMaxDynamicSharedMemorySize, gsmem);
    cudaFuncSetAttribute(gemm_tf32<true>,
                         cudaFuncAttributeMaxDynamicSharedMemorySize, gsmem);

    dim3 gproj(Nn / 128, M / 128);

    // 1. prefill projections (tf32 tensor cores)
    gemm_tf32<false><<<gproj, 256, gsmem>>>(x, wq, q, M, Nn, Kk);
    gemm_tf32<false><<<gproj, 256, gsmem>>>(x, wk, k, M, Nn, Kk);
    gemm_tf32<false><<<gproj, 256, gsmem>>>(x, wv, v, M, Nn, Kk);

    // 2. decode projections (zero + fused k-split atomic)
    decode_zero_kernel<<<(Bz * NHHD + 255) / 256, 256>>>(q1, k1, v1);
    dim3 gdp(NHHD / 256, 16, 3);
    decode_proj_kernel<<<gdp, 256>>>(xn, wq, wk, wv, q1, k1, v1);

    // 3. prefill flash attention (tensor cores)
    const int fsmem = (FQ * QST + FK * QST + FK * VST + FQ * PST) * (int)sizeof(uint32_t);
    cudaFuncSetAttribute(flash_tc_kernel,
                         cudaFuncAttributeMaxDynamicSharedMemorySize, fsmem);
    dim3 gattn(Sn / FQ, NHn, Bz);  // (16,16,2)
    flash_tc_kernel<<<gattn, 256, fsmem>>>(q, k, v, attn);

    // 4. decode attention
    dim3 gdatt(NHn, Bz);
    decode_attn_kernel<<<gdatt, 256>>>(k, v, q1, k1, v1, qkv1);

    // 5. output projections
    gemm_tf32<true><<<gproj, 256, gsmem>>>(attn, wo, out, M, DM, NHHD);
    decode_outproj_kernel<<<DM / 8, 256>>>(qkv1, wo, out + (size_t)Bz * Sn * DM);
}

// round 9
// speedup vs baseline: 4.2915x; 1.2102x over previous
#include <cuda_runtime.h>
#include <cstdint>
#include <math.h>

// Problem constants
#define Bz   2
#define Sn   2048
#define DM   2048
#define NHn  16
#define HD   128
#define NHHD 2048   // NHn*HD

// ------------------- scratch (device globals; no allocation) -------------------
__device__ float g_q   [(size_t)Bz*Sn*NHHD];
__device__ float g_k   [(size_t)Bz*Sn*NHHD];
__device__ float g_v   [(size_t)Bz*Sn*NHHD];
__device__ float g_attn[(size_t)Bz*Sn*NHHD];
__device__ float g_xr  [(size_t)Bz*Sn*DM];     // tf32-rounded x
__device__ float g_wqr [(size_t)DM*NHHD];      // tf32-rounded weights
__device__ float g_wkr [(size_t)DM*NHHD];
__device__ float g_wvr [(size_t)DM*NHHD];
__device__ float g_wor [(size_t)DM*NHHD];
__device__ float g_q1  [Bz*NHHD];
__device__ float g_k1  [Bz*NHHD];
__device__ float g_v1  [Bz*NHHD];
__device__ float g_qkv1[Bz*NHHD];

// ------------------- tf32 helpers -------------------
__device__ __forceinline__ uint32_t tf32r(float x) {
    uint32_t u;
    asm("cvt.rna.tf32.f32 %0, %1;" : "=r"(u) : "f"(x));
    return u;
}

__device__ __forceinline__ void mma_tf32(float* c, const uint32_t* a, uint32_t b0, uint32_t b1) {
    asm volatile("mma.sync.aligned.m16n8k8.row.col.f32.tf32.tf32.f32 "
                 "{%0,%1,%2,%3}, {%4,%5,%6,%7}, {%8,%9}, {%0,%1,%2,%3};"
                 : "+f"(c[0]), "+f"(c[1]), "+f"(c[2]), "+f"(c[3])
                 : "r"(a[0]), "r"(a[1]), "r"(a[2]), "r"(a[3]), "r"(b0), "r"(b1));
}

__device__ __forceinline__ void cp16(uint32_t dst, const void* src) {
    asm volatile("cp.async.cg.shared.global [%0], [%1], 16;" :: "r"(dst), "l"(src));
}
__device__ __forceinline__ void cp_commit() { asm volatile("cp.async.commit_group;"); }
template<int N> __device__ __forceinline__ void cp_wait() {
    asm volatile("cp.async.wait_group %0;" :: "n"(N));
}

// ------------------- tf32 pre-rounding pass -------------------
__global__ __launch_bounds__(256)
void round_tf32_kernel(const float* __restrict__ src, float* __restrict__ dst, int n4)
{
    int i = blockIdx.x * 256 + threadIdx.x;
    if (i < n4) {
        float4 v = ((const float4*)src)[i];
        float4 o;
        o.x = __uint_as_float(tf32r(v.x));
        o.y = __uint_as_float(tf32r(v.y));
        o.z = __uint_as_float(tf32r(v.z));
        o.w = __uint_as_float(tf32r(v.w));
        ((float4*)dst)[i] = o;
    }
}

// ------------------- tf32 tensor-core SGEMM (pre-rounded inputs, 3-stage) -------------------
// C[M,N] = A[M,K] @ B,  B is [K,N] (TRANSB=false) or [N,K] (TRANSB=true, C = A@B^T).
// A and B MUST already be tf32-rounded. Block 128x128x32, 256 threads, 3-stage cp.async.
#define AST 36     // A / B^T smem stride: banks 4g+t4 conflict-free
#define BST 136    // B (NN) smem stride:  banks 8t4+g conflict-free

template<bool TRANSB>
__global__ __launch_bounds__(256, 2)
void gemm_tf32(const float* __restrict__ A, const float* __restrict__ Bm,
               float* __restrict__ C, int M, int N, int K)
{
    constexpr int ASTG = 128 * AST;                       // floats per A stage
    constexpr int BSTG = TRANSB ? 128 * AST : 32 * BST;   // floats per B stage

    extern __shared__ float sm[];
    float* As = sm;                  // 3 * ASTG
    float* Bs = sm + 3 * ASTG;       // 3 * BSTG
    const uint32_t* Au = (const uint32_t*)As;
    const uint32_t* Bu = (const uint32_t*)Bs;

    const int tid  = threadIdx.x;
    const int lane = tid & 31;
    const int wid  = tid >> 5;
    const int wm   = wid >> 2;
    const int wn   = wid & 3;
    const int g    = lane >> 2;
    const int t4   = lane & 3;

    const int m0 = blockIdx.y * 128;
    const int n0 = blockIdx.x * 128;

    const uint32_t s_as = (uint32_t)__cvta_generic_to_shared(As);
    const uint32_t s_bs = (uint32_t)__cvta_generic_to_shared(Bs);

    float acc[4][4][4];
#pragma unroll
    for (int i = 0; i < 4; i++)
#pragma unroll
        for (int j = 0; j < 4; j++)
#pragma unroll
            for (int r = 0; r < 4; r++) acc[i][j][r] = 0.f;

    const int KT = K / 32;

#define LOAD_TILE(stg, k0)                                                       \
    {                                                                            \
        _Pragma("unroll")                                                        \
        for (int it = 0; it < 4; it++) {                                         \
            int idx = tid + it * 256;                                            \
            int mm = idx >> 3;                                                   \
            int k4 = (idx & 7) * 4;                                              \
            cp16(s_as + ((stg) * ASTG + mm * AST + k4) * 4,                      \
                 &A[(size_t)(m0 + mm) * K + (k0) + k4]);                         \
        }                                                                        \
        if constexpr (!TRANSB) {                                                 \
            _Pragma("unroll")                                                    \
            for (int it = 0; it < 4; it++) {                                     \
                int idx = tid + it * 256;                                        \
                int kk = idx >> 5;                                               \
                int n4 = (idx & 31) * 4;                                         \
                cp16(s_bs + ((stg) * BSTG + kk * BST + n4) * 4,                  \
                     &Bm[(size_t)((k0) + kk) * N + n0 + n4]);                    \
            }                                                                    \
        } else {                                                                 \
            _Pragma("unroll")                                                    \
            for (int it = 0; it < 4; it++) {                                     \
                int idx = tid + it * 256;                                        \
                int nn = idx >> 3;                                               \
                int k4 = (idx & 7) * 4;                                          \
                cp16(s_bs + ((stg) * BSTG + nn * AST + k4) * 4,                  \
                     &Bm[(size_t)(n0 + nn) * K + (k0) + k4]);                    \
            }                                                                    \
        }                                                                        \
        cp_commit();                                                             \
    }

    // prologue: stages 0 and 1
    LOAD_TILE(0, 0);
    LOAD_TILE(1, 32);

    for (int kt = 0; kt < KT; kt++) {
        if (kt == KT - 1) cp_wait<0>(); else cp_wait<1>();
        __syncthreads();

        if (kt + 2 < KT) {
            int stg = (kt + 2) % 3;
            LOAD_TILE(stg, (kt + 2) * 32);
        }

        const int stg = kt % 3;
        const uint32_t* Ab = Au + stg * ASTG;
        const uint32_t* Bb = Bu + stg * BSTG;

#pragma unroll
        for (int ks = 0; ks < 4; ks++) {
            const int kk = ks * 8;
            uint32_t a[4][4];
#pragma unroll
            for (int i = 0; i < 4; i++) {
                const int rm = wm * 64 + i * 16;
                const uint32_t* ap = &Ab[(rm + g) * AST + kk + t4];
                a[i][0] = ap[0];
                a[i][1] = ap[8 * AST];
                a[i][2] = ap[4];
                a[i][3] = ap[8 * AST + 4];
            }
#pragma unroll
            for (int j = 0; j < 4; j++) {
                const int cn = wn * 32 + j * 8;
                uint32_t b0, b1;
                if constexpr (!TRANSB) {
                    const uint32_t* bp = &Bb[(kk + t4) * BST + cn + g];
                    b0 = bp[0];
                    b1 = bp[4 * BST];
                } else {
                    const uint32_t* bp = &Bb[(cn + g) * AST + kk + t4];
                    b0 = bp[0];
                    b1 = bp[4];
                }
#pragma unroll
                for (int i = 0; i < 4; i++) mma_tf32(acc[i][j], a[i], b0, b1);
            }
        }
    }

#pragma unroll
    for (int i = 0; i < 4; i++) {
#pragma unroll
        for (int j = 0; j < 4; j++) {
            const int mrow = m0 + wm * 64 + i * 16 + g;
            const int ccol = n0 + wn * 32 + j * 8 + 2 * t4;
            float2 lo = make_float2(acc[i][j][0], acc[i][j][1]);
            float2 hi = make_float2(acc[i][j][2], acc[i][j][3]);
            *(float2*)&C[(size_t)mrow * N + ccol]       = lo;
            *(float2*)&C[(size_t)(mrow + 8) * N + ccol] = hi;
        }
    }
#undef LOAD_TILE
}

// ------------------- tensor-core flash attention prefill (causal) -------------------
#define FQ   128
#define FK   64
#define QST  132
#define VST  136
#define PST  68

__global__ __launch_bounds__(256)
void flash_tc_kernel(const float* __restrict__ Q, const float* __restrict__ K,
                     const float* __restrict__ V, float* __restrict__ O)
{
    extern __shared__ uint32_t smu[];
    uint32_t* Qs = smu;
    uint32_t* Ks = Qs + FQ * QST;
    uint32_t* Vs = Ks + FK * QST;
    uint32_t* Ps = Vs + FK * VST;

    const int tid  = threadIdx.x;
    const int lane = tid & 31;
    const int wid  = tid >> 5;
    const int g    = lane >> 2;
    const int t4   = lane & 3;
    const int rm   = wid * 16;

    const int qt = (int)gridDim.x - 1 - (int)blockIdx.x;
    const int n  = blockIdx.y, b = blockIdx.z;
    const int q0 = qt * FQ;

    const float sc2 = 0.08838834764831845f * 1.4426950408889634f;

#pragma unroll
    for (int it = 0; it < 16; it++) {
        int idx = tid + it * 256;
        int r  = idx >> 5;
        int c4 = (idx & 31) * 4;
        float4 v = *(const float4*)&Q[(((size_t)b * Sn + q0 + r) * NHn + n) * HD + c4];
        uint32_t* d = &Qs[r * QST + c4];
        d[0] = tf32r(v.x); d[1] = tf32r(v.y); d[2] = tf32r(v.z); d[3] = tf32r(v.w);
    }

    float o[16][4];
#pragma unroll
    for (int j = 0; j < 16; j++)
#pragma unroll
        for (int c = 0; c < 4; c++) o[j][c] = 0.f;
    float m0 = -1e30f, m1 = -1e30f, l0 = 0.f, l1 = 0.f;

    const int ktn = 2 * qt + 2;
    for (int kt = 0; kt < ktn; kt++) {
        const int k0 = kt * FK;
        __syncthreads();
#pragma unroll
        for (int it = 0; it < 8; it++) {
            int idx = tid + it * 256;
            int rr = idx >> 5;
            int c4 = (idx & 31) * 4;
            size_t gofs = (((size_t)b * Sn + k0 + rr) * NHn + n) * HD + c4;
            float4 kv = *(const float4*)&K[gofs];
            float4 vv = *(const float4*)&V[gofs];
            uint32_t* dk = &Ks[rr * QST + c4];
            dk[0] = tf32r(kv.x); dk[1] = tf32r(kv.y); dk[2] = tf32r(kv.z); dk[3] = tf32r(kv.w);
            uint32_t* dv = &Vs[rr * VST + c4];
            dv[0] = tf32r(vv.x); dv[1] = tf32r(vv.y); dv[2] = tf32r(vv.z); dv[3] = tf32r(vv.w);
        }
        __syncthreads();

        float s[8][4];
#pragma unroll
        for (int j = 0; j < 8; j++)
#pragma unroll
            for (int c = 0; c < 4; c++) s[j][c] = 0.f;

#pragma unroll
        for (int k8 = 0; k8 < 16; k8++) {
            const int kk = k8 * 8;
            uint32_t a[4];
            a[0] = Qs[(rm + g) * QST + kk + t4];
            a[1] = Qs[(rm + 8 + g) * QST + kk + t4];
            a[2] = Qs[(rm + g) * QST + kk + t4 + 4];
            a[3] = Qs[(rm + 8 + g) * QST + kk + t4 + 4];
#pragma unroll
            for (int j = 0; j < 8; j++) {
                const int cn = j * 8;
                uint32_t b0 = Ks[(cn + g) * QST + kk + t4];
                uint32_t b1 = Ks[(cn + g) * QST + kk + t4 + 4];
                mma_tf32(s[j], a, b0, b1);
            }
        }

        if (kt >= 2 * qt) {
            const int row0 = q0 + rm + g;
#pragma unroll
            for (int j = 0; j < 8; j++) {
                const int col = k0 + j * 8 + 2 * t4;
                if (col     > row0)     s[j][0] = -1e30f;
                if (col + 1 > row0)     s[j][1] = -1e30f;
                if (col     > row0 + 8) s[j][2] = -1e30f;
                if (col + 1 > row0 + 8) s[j][3] = -1e30f;
            }
        }

        float r0 = -1e30f, r1 = -1e30f;
#pragma unroll
        for (int j = 0; j < 8; j++) {
            r0 = fmaxf(r0, fmaxf(s[j][0], s[j][1]));
            r1 = fmaxf(r1, fmaxf(s[j][2], s[j][3]));
        }
        r0 = fmaxf(r0, __shfl_xor_sync(0xffffffffu, r0, 1));
        r0 = fmaxf(r0, __shfl_xor_sync(0xffffffffu, r0, 2));
        r1 = fmaxf(r1, __shfl_xor_sync(0xffffffffu, r1, 1));
        r1 = fmaxf(r1, __shfl_xor_sync(0xffffffffu, r1, 2));

        float mn0 = fmaxf(m0, r0), mn1 = fmaxf(m1, r1);
        float al0 = exp2f((m0 - mn0) * sc2), al1 = exp2f((m1 - mn1) * sc2);
        m0 = mn0; m1 = mn1;

#pragma unroll
        for (int j = 0; j < 16; j++) {
            o[j][0] *= al0; o[j][1] *= al0;
            o[j][2] *= al1; o[j][3] *= al1;
        }

        float ls0 = 0.f, ls1 = 0.f;
#pragma unroll
        for (int j = 0; j < 8; j++) {
            float p0 = exp2f((s[j][0] - m0) * sc2);
            float p1 = exp2f((s[j][1] - m0) * sc2);
            float p2 = exp2f((s[j][2] - m1) * sc2);
            float p3 = exp2f((s[j][3] - m1) * sc2);
            ls0 += p0 + p1; ls1 += p2 + p3;
            const int cn = j * 8 + 2 * t4;
            uint2 lo = make_uint2(tf32r(p0), tf32r(p1));
            uint2 hi = make_uint2(tf32r(p2), tf32r(p3));
            *(uint2*)&Ps[(rm + g) * PST + cn]     = lo;
            *(uint2*)&Ps[(rm + 8 + g) * PST + cn] = hi;
        }
        ls0 += __shfl_xor_sync(0xffffffffu, ls0, 1);
        ls0 += __shfl_xor_sync(0xffffffffu, ls0, 2);
        ls1 += __shfl_xor_sync(0xffffffffu, ls1, 1);
        ls1 += __shfl_xor_sync(0xffffffffu, ls1, 2);
        l0 = l0 * al0 + ls0;
        l1 = l1 * al1 + ls1;

        __syncwarp();

#pragma unroll
        for (int k8 = 0; k8 < 8; k8++) {
            const int kk = k8 * 8;
            uint32_t a[4];
            a[0] = Ps[(rm + g) * PST + kk + t4];
            a[1] = Ps[(rm + 8 + g) * PST + kk + t4];
            a[2] = Ps[(rm + g) * PST + kk + t4 + 4];
            a[3] = Ps[(rm + 8 + g) * PST + kk + t4 + 4];
#pragma unroll
            for (int j = 0; j < 16; j++) {
                const int cn = j * 8;
                uint32_t b0 = Vs[(kk + t4) * VST + cn + g];
                uint32_t b1 = Vs[(kk + t4 + 4) * VST + cn + g];
                mma_tf32(o[j], a, b0, b1);
            }
        }
    }

    // epilogue: write tf32-rounded O (feeds the NT gemm directly, no extra pass)
    const float i0 = 1.f / l0, i1 = 1.f / l1;
    const int row0 = q0 + rm + g;
#pragma unroll
    for (int j = 0; j < 16; j++) {
        const int col = j * 8 + 2 * t4;
        float2 lo = make_float2(__uint_as_float(tf32r(o[j][0] * i0)),
                                __uint_as_float(tf32r(o[j][1] * i0)));
        float2 hi = make_float2(__uint_as_float(tf32r(o[j][2] * i1)),
                                __uint_as_float(tf32r(o[j][3] * i1)));
        *(float2*)&O[(((size_t)b * Sn + row0) * NHn + n) * HD + col]     = lo;
        *(float2*)&O[(((size_t)b * Sn + row0 + 8) * NHn + n) * HD + col] = hi;
    }
}

// ------------------- decode projections -------------------
__global__ void decode_zero_kernel(float* q1, float* k1, float* v1)
{
    int i = blockIdx.x * 256 + threadIdx.x;
    if (i < Bz * NHHD) { q1[i] = 0.f; k1[i] = 0.f; v1[i] = 0.f; }
}

__global__ __launch_bounds__(256)
void decode_proj_kernel(const float* __restrict__ xn,
                        const float* __restrict__ wq, const float* __restrict__ wk,
                        const float* __restrict__ wv,
                        float* __restrict__ q1, float* __restrict__ k1,
                        float* __restrict__ v1)
{
    __shared__ float xs[2][128];
    const int tid = threadIdx.x;
    const int pz = blockIdx.z;
    const float* w = (pz == 0) ? wq : (pz == 1) ? wk : wv;
    float* out     = (pz == 0) ? q1 : (pz == 1) ? k1 : v1;

    const int k0 = blockIdx.y * 128;
    const int nn = blockIdx.x * 256 + tid;

    { int bb = tid >> 7, kk = tid & 127; xs[bb][kk] = xn[(size_t)bb * DM + k0 + kk]; }
    __syncthreads();

    float a0 = 0.f, a1 = 0.f;
#pragma unroll 8
    for (int kk = 0; kk < 128; kk++) {
        float wv_ = w[(size_t)(k0 + kk) * NHHD + nn];
        a0 += xs[0][kk] * wv_;
        a1 += xs[1][kk] * wv_;
    }
    atomicAdd(&out[nn], a0);
    atomicAdd(&out[NHHD + nn], a1);
}

__global__ __launch_bounds__(256)
void decode_outproj_kernel(const float* __restrict__ qkv1, const float* __restrict__ wo,
                           float* __restrict__ out)
{
    __shared__ float qs[2][NHHD];
    const int tid = threadIdx.x;
    const int lane = tid & 31, wid = tid >> 5;
    const int d = blockIdx.x * 8 + wid;
    for (int i = tid; i < 2 * NHHD; i += 256)
        qs[i >> 11][i & (NHHD - 1)] = qkv1[i];
    __syncthreads();
    float a0 = 0.f, a1 = 0.f;
#pragma unroll
    for (int nh = lane * 4; nh < NHHD; nh += 128) {
        float4 wv = *(const float4*)&wo[(size_t)d * NHHD + nh];
        a0 += qs[0][nh] * wv.x + qs[0][nh + 1] * wv.y + qs[0][nh + 2] * wv.z + qs[0][nh + 3] * wv.w;
        a1 += qs[1][nh] * wv.x + qs[1][nh + 1] * wv.y + qs[1][nh + 2] * wv.z + qs[1][nh + 3] * wv.w;
    }
#pragma unroll
    for (int s = 16; s; s >>= 1) {
        a0 += __shfl_xor_sync(0xffffffffu, a0, s);
        a1 += __shfl_xor_sync(0xffffffffu, a1, s);
    }
    if (lane == 0) {
        out[d]      = a0;
        out[DM + d] = a1;
    }
}

// ------------------- decode attention -------------------
__global__ __launch_bounds__(256)
void decode_attn_kernel(const float* __restrict__ Kc, const float* __restrict__ Vc,
                        const float* __restrict__ q1, const float* __restrict__ k1,
                        const float* __restrict__ v1, float* __restrict__ out)
{
    __shared__ float qs[HD];
    __shared__ float sc[Sn + 1];
    __shared__ float red[256];
    __shared__ float oacc[2][HD];

    int n = blockIdx.x, b = blockIdx.y;
    int tid = threadIdx.x;
    const float scale = 0.08838834764831845f;

    if (tid < HD) qs[tid] = q1[(size_t)b * NHHD + n * HD + tid];
    __syncthreads();

    for (int t = tid; t <= Sn; t += 256) {
        const float* kp = (t < Sn) ? &Kc[(((size_t)b * Sn + t) * NHn + n) * HD]
                                   : &k1[(size_t)b * NHHD + n * HD];
        float acc = 0.f;
#pragma unroll
        for (int d = 0; d < HD; d += 4) {
            float4 kv = *(const float4*)&kp[d];
            acc += qs[d] * kv.x + qs[d + 1] * kv.y + qs[d + 2] * kv.z + qs[d + 3] * kv.w;
        }
        sc[t] = acc * scale;
    }
    __syncthreads();

    float mx = -1e30f;
    for (int t = tid; t <= Sn; t += 256) mx = fmaxf(mx, sc[t]);
    red[tid] = mx;
    __syncthreads();
    for (int s = 128; s > 0; s >>= 1) {
        if (tid < s) red[tid] = fmaxf(red[tid], red[tid + s]);
        __syncthreads();
    }
    mx = red[0];
    __syncthreads();

    float ls = 0.f;
    for (int t = tid; t <= Sn; t += 256) {
        float p = __expf(sc[t] - mx);
        sc[t] = p;
        ls += p;
    }
    red[tid] = ls;
    __syncthreads();
    for (int s = 128; s > 0; s >>= 1) {
        if (tid < s) red[tid] += red[tid + s];
        __syncthreads();
    }
    float inv = 1.f / red[0];
    __syncthreads();

    int grp = tid >> 7;
    int h   = tid & 127;
    float acc = 0.f;
#pragma unroll 4
    for (int t = grp; t < Sn; t += 2)
        acc += sc[t] * Vc[(((size_t)b * Sn + t) * NHn + n) * HD + h];
    if (grp == 1) acc += sc[Sn] * v1[(size_t)b * NHHD + n * HD + h];
    oacc[grp][h] = acc;
    __syncthreads();
    if (tid < HD)
        out[(size_t)b * NHHD + n * HD + tid] = (oacc[0][tid] + oacc[1][tid]) * inv;
}

// ------------------- launch -------------------
extern "C" void kernel_launch(void* const* d_in, const int* in_sizes, int n_in,
                              void* d_out, int out_size)
{
    (void)in_sizes; (void)n_in; (void)out_size;
    const float* x  = (const float*)d_in[0];
    const float* xn = (const float*)d_in[1];
    const float* wq = (const float*)d_in[2];
    const float* wk = (const float*)d_in[3];
    const float* wv = (const float*)d_in[4];
    const float* wo = (const float*)d_in[5];
    float* out = (float*)d_out;

    float *q, *k, *v, *attn, *xr, *wqr, *wkr, *wvr, *wor, *q1, *k1, *v1, *qkv1;
    cudaGetSymbolAddress((void**)&q,    g_q);
    cudaGetSymbolAddress((void**)&k,    g_k);
    cudaGetSymbolAddress((void**)&v,    g_v);
    cudaGetSymbolAddress((void**)&attn, g_attn);
    cudaGetSymbolAddress((void**)&xr,   g_xr);
    cudaGetSymbolAddress((void**)&wqr,  g_wqr);
    cudaGetSymbolAddress((void**)&wkr,  g_wkr);
    cudaGetSymbolAddress((void**)&wvr,  g_wvr);
    cudaGetSymbolAddress((void**)&wor,  g_wor);
    cudaGetSymbolAddress((void**)&q1,   g_q1);
    cudaGetSymbolAddress((void**)&k1,   g_k1);
    cudaGetSymbolAddress((void**)&v1,   g_v1);
    cudaGetSymbolAddress((void**)&qkv1, g_qkv1);

    const int M  = Bz * Sn;    // 4096
    const int Nn = NHHD;       // 2048
    const int Kk = DM;         // 2048

    // 0. tf32 pre-rounding passes
    const int xn4 = (Bz * Sn * DM) / 4;    // 2,097,152
    const int wn4 = (DM * NHHD) / 4;       // 1,048,576
    round_tf32_kernel<<<xn4 / 256, 256>>>(x,  xr,  xn4);
    round_tf32_kernel<<<wn4 / 256, 256>>>(wq, wqr, wn4);
    round_tf32_kernel<<<wn4 / 256, 256>>>(wk, wkr, wn4);
    round_tf32_kernel<<<wn4 / 256, 256>>>(wv, wvr, wn4);
    round_tf32_kernel<<<wn4 / 256, 256>>>(wo, wor, wn4);

    // GEMM smem: 3-stage
    const int gsmem_nn = 3 * (128 * AST + 32 * BST) * (int)sizeof(float);   // 107,520
    const int gsmem_nt = 3 * (128 * AST + 128 * AST) * (int)sizeof(float);  // 110,592
    cudaFuncSetAttribute(gemm_tf32<false>,
                         cudaFuncAttributeMaxDynamicSharedMemorySize, gsmem_nn);
    cudaFuncSetAttribute(gemm_tf32<true>,
                         cudaFuncAttributeMaxDynamicSharedMemorySize, gsmem_nt);

    dim3 gproj(Nn / 128, M / 128);

    // 1. prefill projections (tf32 tensor cores, pre-rounded operands)
    gemm_tf32<false><<<gproj, 256, gsmem_nn>>>(xr, wqr, q, M, Nn, Kk);
    gemm_tf32<false><<<gproj, 256, gsmem_nn>>>(xr, wkr, k, M, Nn, Kk);
    gemm_tf32<false><<<gproj, 256, gsmem_nn>>>(xr, wvr, v, M, Nn, Kk);

    // 2. decode projections
    decode_zero_kernel<<<(Bz * NHHD + 255) / 256, 256>>>(q1, k1, v1);
    dim3 gdp(NHHD / 256, 16, 3);
    decode_proj_kernel<<<gdp, 256>>>(xn, wq, wk, wv, q1, k1, v1);

    // 3. prefill flash attention (tensor cores)
    const int fsmem = (FQ * QST + FK * QST + FK * VST + FQ * PST) * (int)sizeof(uint32_t);
    cudaFuncSetAttribute(flash_tc_kernel,
                         cudaFuncAttributeMaxDynamicSharedMemorySize, fsmem);
    dim3 gattn(Sn / FQ, NHn, Bz);
    flash_tc_kernel<<<gattn, 256, fsmem>>>(q, k, v, attn);

    // 4. decode attention
    dim3 gdatt(NHn, Bz);
    decode_attn_kernel<<<gdatt, 256>>>(k, v, q1, k1, v1, qkv1);

    // 5. output projections
    gemm_tf32<true><<<gproj, 256, gsmem_nt>>>(attn, wor, out, M, DM, NHHD);
    decode_outproj_kernel<<<DM / 8, 256>>>(qkv1, wo, out + (size_t)Bz * Sn * DM);
}

// round 14
// speedup vs baseline: 6.9643x; 1.6228x over previous
#include <cuda_runtime.h>
#include <cuda_fp16.h>
#include <cstdint>
#include <math.h>

// Problem constants
#define Bz   2
#define Sn   2048
#define DM   2048
#define NHn  16
#define HD   128
#define NHHD 2048   // NHn*HD

// ------------------- scratch (device globals; no allocation) -------------------
__device__ float  g_q    [(size_t)Bz*Sn*NHHD];
__device__ float  g_k    [(size_t)Bz*Sn*NHHD];
__device__ float  g_v    [(size_t)Bz*Sn*NHHD];
__device__ __half g_attnh[(size_t)Bz*Sn*NHHD];
__device__ __half g_xh   [(size_t)Bz*Sn*DM];     // fp16 x
__device__ __half g_wqh  [(size_t)DM*NHHD];      // fp16 weights, [N,K]
__device__ __half g_wkh  [(size_t)DM*NHHD];
__device__ __half g_wvh  [(size_t)DM*NHHD];
__device__ __half g_woh  [(size_t)DM*NHHD];      // wo fp16 (already [N,K])
__device__ float  g_q1   [Bz*NHHD];
__device__ float  g_k1   [Bz*NHHD];
__device__ float  g_v1   [Bz*NHHD];
__device__ float  g_qkv1 [Bz*NHHD];

// ------------------- helpers -------------------
__device__ __forceinline__ void mma_f16(float* c, const uint32_t* a, uint32_t b0, uint32_t b1) {
    asm volatile("mma.sync.aligned.m16n8k16.row.col.f32.f16.f16.f32 "
                 "{%0,%1,%2,%3}, {%4,%5,%6,%7}, {%8,%9}, {%0,%1,%2,%3};"
                 : "+f"(c[0]), "+f"(c[1]), "+f"(c[2]), "+f"(c[3])
                 : "r"(a[0]), "r"(a[1]), "r"(a[2]), "r"(a[3]), "r"(b0), "r"(b1));
}
__device__ __forceinline__ void cp16(uint32_t dst, const void* src) {
    asm volatile("cp.async.cg.shared.global [%0], [%1], 16;" :: "r"(dst), "l"(src));
}
__device__ __forceinline__ void cp_commit() { asm volatile("cp.async.commit_group;"); }
template<int N> __device__ __forceinline__ void cp_wait() {
    asm volatile("cp.async.wait_group %0;" :: "n"(N));
}
__device__ __forceinline__ uint32_t h2u(__half2 h) {
    return *(uint32_t*)&h;
}

// ------------------- fp16 conversion passes -------------------
__global__ __launch_bounds__(256)
void conv_half_kernel(const float* __restrict__ src, __half* __restrict__ dst, int n4)
{
    int i = blockIdx.x * 256 + threadIdx.x;
    if (i < n4) {
        float4 v = ((const float4*)src)[i];
        __half2 lo = __floats2half2_rn(v.x, v.y);
        __half2 hi = __floats2half2_rn(v.z, v.w);
        uint2 o = make_uint2(h2u(lo), h2u(hi));
        ((uint2*)dst)[i] = o;
    }
}

// wt[n][k] = half(w[k][n]); w is [DM, NHHD]. grid (64, 64, 3), block 256 (32x8)
__global__ __launch_bounds__(256)
void transpose_half_kernel(const float* __restrict__ wq, const float* __restrict__ wk,
                           const float* __restrict__ wv,
                           __half* __restrict__ qt, __half* __restrict__ kt,
                           __half* __restrict__ vt)
{
    __shared__ float t[32][33];
    const int z = blockIdx.z;
    const float* w = (z == 0) ? wq : (z == 1) ? wk : wv;
    __half* wt     = (z == 0) ? qt : (z == 1) ? kt : vt;
    const int k0 = blockIdx.x * 32, n0 = blockIdx.y * 32;
    const int tx = threadIdx.x & 31, ty = threadIdx.x >> 5;
#pragma unroll
    for (int i = 0; i < 32; i += 8)
        t[ty + i][tx] = w[(size_t)(k0 + ty + i) * NHHD + n0 + tx];
    __syncthreads();
#pragma unroll
    for (int i = 0; i < 32; i += 8)
        wt[(size_t)(n0 + ty + i) * DM + k0 + tx] = __float2half_rn(t[tx][ty + i]);
}

// ------------------- fp16 tensor-core GEMM (NT) -------------------
// C[4096,2048] = A[4096,2048] @ Bt[2048,2048]^T; A,Bt fp16 k-major, C fp32.
// Block 128x128, K-chunk 64 halves (32 f16x2 words/row), 3-stage cp.async, 2 CTA/SM.
#define GK   2048
#define GN   2048
#define HAST 36                       // smem row stride in words (4 mod 32 -> banks 4g+t4)
#define WPT  (128 * HAST)             // words per tile
#define STGW (2 * WPT)                // words per stage (A + B)
#define NCH  (GK / 64)                // 32 chunks

__global__ __launch_bounds__(256, 2)
void gemm_f16(const __half* __restrict__ A, const __half* __restrict__ Bt,
              float* __restrict__ C)
{
    extern __shared__ uint32_t smw[];
    const uint32_t sb = (uint32_t)__cvta_generic_to_shared(smw);

    const int tid  = threadIdx.x;
    const int lane = tid & 31;
    const int wid  = tid >> 5;
    const int wm   = wid >> 2;     // 0..1
    const int wn   = wid & 3;      // 0..3
    const int g    = lane >> 2;
    const int t4   = lane & 3;

    const int m0 = blockIdx.y * 128;
    const int n0 = blockIdx.x * 128;

    float acc[4][4][4];
#pragma unroll
    for (int i = 0; i < 4; i++)
#pragma unroll
        for (int j = 0; j < 4; j++)
#pragma unroll
            for (int r = 0; r < 4; r++) acc[i][j][r] = 0.f;

#define FILLH(cch, stg)                                                          \
    {                                                                            \
        _Pragma("unroll")                                                        \
        for (int it = 0; it < 4; it++) {                                         \
            int idx = tid + it * 256;            /* 1024 A segs */               \
            int row = idx >> 3, s16 = idx & 7;                                   \
            cp16(sb + ((stg) * STGW + row * HAST + s16 * 4) * 4,                 \
                 A + (size_t)(m0 + row) * GK + (cch) * 64 + s16 * 8);            \
        }                                                                        \
        _Pragma("unroll")                                                        \
        for (int it = 0; it < 4; it++) {                                         \
            int idx = tid + it * 256;            /* 1024 B segs */               \
            int row = idx >> 3, s16 = idx & 7;                                   \
            cp16(sb + ((stg) * STGW + WPT + row * HAST + s16 * 4) * 4,           \
                 Bt + (size_t)(n0 + row) * GK + (cch) * 64 + s16 * 8);           \
        }                                                                        \
        cp_commit();                                                             \
    }

    FILLH(0, 0);
    FILLH(1, 1);

    for (int c = 0; c < NCH; c++) {
        if (c < NCH - 1) cp_wait<1>(); else cp_wait<0>();
        __syncthreads();
        if (c + 2 < NCH) FILLH(c + 2, (c + 2) % 3);

        const uint32_t* Ab = smw + (c % 3) * STGW;
        const uint32_t* Bb = Ab + WPT;

#pragma unroll
        for (int ks = 0; ks < 4; ks++) {
            const int kw = ks * 8;
            uint32_t a[4][4];
#pragma unroll
            for (int i = 0; i < 4; i++) {
                const int rm = wm * 64 + i * 16;
                const uint32_t* ap = &Ab[(rm + g) * HAST + kw + t4];
                a[i][0] = ap[0];
                a[i][1] = ap[8 * HAST];
                a[i][2] = ap[4];
                a[i][3] = ap[8 * HAST + 4];
            }
#pragma unroll
            for (int j = 0; j < 4; j++) {
                const int cn = wn * 32 + j * 8;
                const uint32_t* bp = &Bb[(cn + g) * HAST + kw + t4];
                uint32_t b0 = bp[0];
                uint32_t b1 = bp[4];
#pragma unroll
                for (int i = 0; i < 4; i++) mma_f16(acc[i][j], a[i], b0, b1);
            }
        }
    }

#pragma unroll
    for (int i = 0; i < 4; i++) {
#pragma unroll
        for (int j = 0; j < 4; j++) {
            const int mrow = m0 + wm * 64 + i * 16 + g;
            const int ccol = n0 + wn * 32 + j * 8 + 2 * t4;
            float2 lo = make_float2(acc[i][j][0], acc[i][j][1]);
            float2 hi = make_float2(acc[i][j][2], acc[i][j][3]);
            *(float2*)&C[(size_t)mrow * GN + ccol]       = lo;
            *(float2*)&C[(size_t)(mrow + 8) * GN + ccol] = hi;
        }
    }
#undef FILLH
}

// ------------------- fp16 tensor-core flash attention prefill (causal) -------------------
// Q,K,V fp32 in; converts to fp16 in smem; O written as fp16 (feeds output GEMM).
#define FQ   128
#define FK   64
#define QST  68    // Qs/Ks word stride (HD/2=64 words + 4 pad; 4 mod 32)
#define VST  136   // Vs word stride (kp rows of 128 n-words + 8 pad; 8 mod 32)
#define PST  36    // Ps word stride (FK/2=32 words + 4 pad; 4 mod 32)

__global__ __launch_bounds__(256)
void flash_f16_kernel(const float* __restrict__ Q, const float* __restrict__ K,
                      const float* __restrict__ V, __half* __restrict__ O)
{
    extern __shared__ uint32_t smu[];
    uint32_t* Qs = smu;                  // FQ * QST
    uint32_t* Ks = Qs + FQ * QST;        // FK * QST
    uint32_t* Vs = Ks + FK * QST;        // (FK/2) * VST
    uint32_t* Ps = Vs + (FK / 2) * VST;  // FQ * PST

    const int tid  = threadIdx.x;
    const int lane = tid & 31;
    const int wid  = tid >> 5;
    const int g    = lane >> 2;
    const int t4   = lane & 3;
    const int rm   = wid * 16;

    const int qt = (int)gridDim.x - 1 - (int)blockIdx.x;   // heavy blocks first
    const int n  = blockIdx.y, b = blockIdx.z;
    const int q0 = qt * FQ;

    const float sc2 = 0.08838834764831845f * 1.4426950408889634f;  // scale*log2(e)

    // load Q tile (fp32 -> f16x2 words)
#pragma unroll
    for (int it = 0; it < 16; it++) {
        int idx = tid + it * 256;
        int r  = idx >> 5;
        int c4 = (idx & 31) * 4;
        float4 v = *(const float4*)&Q[(((size_t)b * Sn + q0 + r) * NHn + n) * HD + c4];
        uint2 w = make_uint2(h2u(__floats2half2_rn(v.x, v.y)),
                             h2u(__floats2half2_rn(v.z, v.w)));
        *(uint2*)&Qs[r * QST + c4 / 2] = w;
    }

    float o[16][4];
#pragma unroll
    for (int j = 0; j < 16; j++)
#pragma unroll
        for (int c = 0; c < 4; c++) o[j][c] = 0.f;
    float m0 = -1e30f, m1 = -1e30f, l0 = 0.f, l1 = 0.f;

    const int ktn = 2 * qt + 2;
    for (int kt = 0; kt < ktn; kt++) {
        const int k0 = kt * FK;
        __syncthreads();
        // K tile: rows = key tokens (n-dim), k-major words
#pragma unroll
        for (int it = 0; it < 8; it++) {
            int idx = tid + it * 256;
            int rr = idx >> 5;
            int c4 = (idx & 31) * 4;
            float4 kv = *(const float4*)&K[(((size_t)b * Sn + k0 + rr) * NHn + n) * HD + c4];
            uint2 w = make_uint2(h2u(__floats2half2_rn(kv.x, kv.y)),
                                 h2u(__floats2half2_rn(kv.z, kv.w)));
            *(uint2*)&Ks[rr * QST + c4 / 2] = w;
        }
        // V tile: pack k-pairs across token rows: Vs[kp][n] = {V[2kp][n], V[2kp+1][n]}
#pragma unroll
        for (int it = 0; it < 4; it++) {
            int idx = tid + it * 256;
            int kp = idx >> 5;
            int c4 = (idx & 31) * 4;
            size_t g0 = (((size_t)b * Sn + k0 + 2 * kp) * NHn + n) * HD + c4;
            float4 va = *(const float4*)&V[g0];
            float4 vb = *(const float4*)&V[g0 + (size_t)NHn * HD];
            uint4 w = make_uint4(h2u(__floats2half2_rn(va.x, vb.x)),
                                 h2u(__floats2half2_rn(va.y, vb.y)),
                                 h2u(__floats2half2_rn(va.z, vb.z)),
                                 h2u(__floats2half2_rn(va.w, vb.w)));
            *(uint4*)&Vs[kp * VST + c4] = w;
        }
        __syncthreads();

        // ---- S = Q K^T (warp: 16 rows x 64 cols); HD=128 -> 8 k16 steps ----
        float s[8][4];
#pragma unroll
        for (int j = 0; j < 8; j++)
#pragma unroll
            for (int c = 0; c < 4; c++) s[j][c] = 0.f;

#pragma unroll
        for (int ks = 0; ks < 8; ks++) {
            const int kw = ks * 8;
            uint32_t a[4];
            a[0] = Qs[(rm + g) * QST + kw + t4];
            a[1] = Qs[(rm + 8 + g) * QST + kw + t4];
            a[2] = Qs[(rm + g) * QST + kw + t4 + 4];
            a[3] = Qs[(rm + 8 + g) * QST + kw + t4 + 4];
#pragma unroll
            for (int j = 0; j < 8; j++) {
                const int cn = j * 8;
                uint32_t b0 = Ks[(cn + g) * QST + kw + t4];
                uint32_t b1 = Ks[(cn + g) * QST + kw + t4 + 4];
                mma_f16(s[j], a, b0, b1);
            }
        }

        // ---- causal mask (diagonal tiles only) ----
        if (kt >= 2 * qt) {
            const int row0 = q0 + rm + g;
#pragma unroll
            for (int j = 0; j < 8; j++) {
                const int col = k0 + j * 8 + 2 * t4;
                if (col     > row0)     s[j][0] = -1e30f;
                if (col + 1 > row0)     s[j][1] = -1e30f;
                if (col     > row0 + 8) s[j][2] = -1e30f;
                if (col + 1 > row0 + 8) s[j][3] = -1e30f;
            }
        }

        // ---- online softmax ----
        float r0 = -1e30f, r1 = -1e30f;
#pragma unroll
        for (int j = 0; j < 8; j++) {
            r0 = fmaxf(r0, fmaxf(s[j][0], s[j][1]));
            r1 = fmaxf(r1, fmaxf(s[j][2], s[j][3]));
        }
        r0 = fmaxf(r0, __shfl_xor_sync(0xffffffffu, r0, 1));
        r0 = fmaxf(r0, __shfl_xor_sync(0xffffffffu, r0, 2));
        r1 = fmaxf(r1, __shfl_xor_sync(0xffffffffu, r1, 1));
        r1 = fmaxf(r1, __shfl_xor_sync(0xffffffffu, r1, 2));

        float mn0 = fmaxf(m0, r0), mn1 = fmaxf(m1, r1);
        float al0 = exp2f((m0 - mn0) * sc2), al1 = exp2f((m1 - mn1) * sc2);
        m0 = mn0; m1 = mn1;

#pragma unroll
        for (int j = 0; j < 16; j++) {
            o[j][0] *= al0; o[j][1] *= al0;
            o[j][2] *= al1; o[j][3] *= al1;
        }

        float ls0 = 0.f, ls1 = 0.f;
#pragma unroll
        for (int j = 0; j < 8; j++) {
            float p0 = exp2f((s[j][0] - m0) * sc2);
            float p1 = exp2f((s[j][1] - m0) * sc2);
            float p2 = exp2f((s[j][2] - m1) * sc2);
            float p3 = exp2f((s[j][3] - m1) * sc2);
            ls0 += p0 + p1; ls1 += p2 + p3;
            Ps[(rm + g) * PST + j * 4 + t4]     = h2u(__floats2half2_rn(p0, p1));
            Ps[(rm + 8 + g) * PST + j * 4 + t4] = h2u(__floats2half2_rn(p2, p3));
        }
        ls0 += __shfl_xor_sync(0xffffffffu, ls0, 1);
        ls0 += __shfl_xor_sync(0xffffffffu, ls0, 2);
        ls1 += __shfl_xor_sync(0xffffffffu, ls1, 1);
        ls1 += __shfl_xor_sync(0xffffffffu, ls1, 2);
        l0 = l0 * al0 + ls0;
        l1 = l1 * al1 + ls1;

        __syncwarp();  // P rows warp-private; quad cross-reads only

        // ---- O += P V (warp: 16 rows x 128 cols); FK=64 -> 4 k16 steps ----
#pragma unroll
        for (int ks = 0; ks < 4; ks++) {
            const int kw = ks * 8;
            uint32_t a[4];
            a[0] = Ps[(rm + g) * PST + kw + t4];
            a[1] = Ps[(rm + 8 + g) * PST + kw + t4];
            a[2] = Ps[(rm + g) * PST + kw + t4 + 4];
            a[3] = Ps[(rm + 8 + g) * PST + kw + t4 + 4];
#pragma unroll
            for (int j = 0; j < 16; j++) {
                const int cn = j * 8;
                uint32_t b0 = Vs[(kw + t4) * VST + cn + g];
                uint32_t b1 = Vs[(kw + 4 + t4) * VST + cn + g];
                mma_f16(o[j], a, b0, b1);
            }
        }
    }

    // epilogue: fp16 output (cols are even pairs -> half2 stores)
    const float i0 = 1.f / l0, i1 = 1.f / l1;
    const int row0 = q0 + rm + g;
#pragma unroll
    for (int j = 0; j < 16; j++) {
        const int col = j * 8 + 2 * t4;
        __half2 lo = __floats2half2_rn(o[j][0] * i0, o[j][1] * i0);
        __half2 hi = __floats2half2_rn(o[j][2] * i1, o[j][3] * i1);
        *(__half2*)&O[(((size_t)b * Sn + row0) * NHn + n) * HD + col]     = lo;
        *(__half2*)&O[(((size_t)b * Sn + row0 + 8) * NHn + n) * HD + col] = hi;
    }
}

// ------------------- decode projections -------------------
__global__ void decode_zero_kernel(float* q1, float* k1, float* v1)
{
    int i = blockIdx.x * 256 + threadIdx.x;
    if (i < Bz * NHHD) { q1[i] = 0.f; k1[i] = 0.f; v1[i] = 0.f; }
}

__global__ __launch_bounds__(256)
void decode_proj_kernel(const float* __restrict__ xn,
                        const float* __restrict__ wq, const float* __restrict__ wk,
                        const float* __restrict__ wv,
                        float* __restrict__ q1, float* __restrict__ k1,
                        float* __restrict__ v1)
{
    __shared__ float xs[2][128];
    const int tid = threadIdx.x;
    const int pz = blockIdx.z;
    const float* w = (pz == 0) ? wq : (pz == 1) ? wk : wv;
    float* out     = (pz == 0) ? q1 : (pz == 1) ? k1 : v1;

    const int k0 = blockIdx.y * 128;
    const int nn = blockIdx.x * 256 + tid;

    { int bb = tid >> 7, kk = tid & 127; xs[bb][kk] = xn[(size_t)bb * DM + k0 + kk]; }
    __syncthreads();

    float a0 = 0.f, a1 = 0.f;
#pragma unroll 8
    for (int kk = 0; kk < 128; kk++) {
        float wv_ = w[(size_t)(k0 + kk) * NHHD + nn];
        a0 += xs[0][kk] * wv_;
        a1 += xs[1][kk] * wv_;
    }
    atomicAdd(&out[nn], a0);
    atomicAdd(&out[NHHD + nn], a1);
}

__global__ __launch_bounds__(256)
void decode_outproj_kernel(const float* __restrict__ qkv1, const float* __restrict__ wo,
                           float* __restrict__ out)
{
    __shared__ float qs[2][NHHD];
    const int tid = threadIdx.x;
    const int lane = tid & 31, wid = tid >> 5;
    const int d = blockIdx.x * 8 + wid;
    for (int i = tid; i < 2 * NHHD; i += 256)
        qs[i >> 11][i & (NHHD - 1)] = qkv1[i];
    __syncthreads();
    float a0 = 0.f, a1 = 0.f;
#pragma unroll
    for (int nh = lane * 4; nh < NHHD; nh += 128) {
        float4 wv = *(const float4*)&wo[(size_t)d * NHHD + nh];
        a0 += qs[0][nh] * wv.x + qs[0][nh + 1] * wv.y + qs[0][nh + 2] * wv.z + qs[0][nh + 3] * wv.w;
        a1 += qs[1][nh] * wv.x + qs[1][nh + 1] * wv.y + qs[1][nh + 2] * wv.z + qs[1][nh + 3] * wv.w;
    }
#pragma unroll
    for (int s = 16; s; s >>= 1) {
        a0 += __shfl_xor_sync(0xffffffffu, a0, s);
        a1 += __shfl_xor_sync(0xffffffffu, a1, s);
    }
    if (lane == 0) {
        out[d]      = a0;
        out[DM + d] = a1;
    }
}

// ------------------- decode attention -------------------
__global__ __launch_bounds__(256)
void decode_attn_kernel(const float* __restrict__ Kc, const float* __restrict__ Vc,
                        const float* __restrict__ q1, const float* __restrict__ k1,
                        const float* __restrict__ v1, float* __restrict__ out)
{
    __shared__ float qs[HD];
    __shared__ float sc[Sn + 1];
    __shared__ float red[256];
    __shared__ float oacc[2][HD];

    int n = blockIdx.x, b = blockIdx.y;
    int tid = threadIdx.x;
    const float scale = 0.08838834764831845f;

    if (tid < HD) qs[tid] = q1[(size_t)b * NHHD + n * HD + tid];
    __syncthreads();

    for (int t = tid; t <= Sn; t += 256) {
        const float* kp = (t < Sn) ? &Kc[(((size_t)b * Sn + t) * NHn + n) * HD]
                                   : &k1[(size_t)b * NHHD + n * HD];
        float acc = 0.f;
#pragma unroll
        for (int d = 0; d < HD; d += 4) {
            float4 kv = *(const float4*)&kp[d];
            acc += qs[d] * kv.x + qs[d + 1] * kv.y + qs[d + 2] * kv.z + qs[d + 3] * kv.w;
        }
        sc[t] = acc * scale;
    }
    __syncthreads();

    float mx = -1e30f;
    for (int t = tid; t <= Sn; t += 256) mx = fmaxf(mx, sc[t]);
    red[tid] = mx;
    __syncthreads();
    for (int s = 128; s > 0; s >>= 1) {
        if (tid < s) red[tid] = fmaxf(red[tid], red[tid + s]);
        __syncthreads();
    }
    mx = red[0];
    __syncthreads();

    float ls = 0.f;
    for (int t = tid; t <= Sn; t += 256) {
        float p = __expf(sc[t] - mx);
        sc[t] = p;
        ls += p;
    }
    red[tid] = ls;
    __syncthreads();
    for (int s = 128; s > 0; s >>= 1) {
        if (tid < s) red[tid] += red[tid + s];
        __syncthreads();
    }
    float inv = 1.f / red[0];
    __syncthreads();

    int grp = tid >> 7;
    int h   = tid & 127;
    float acc = 0.f;
#pragma unroll 4
    for (int t = grp; t < Sn; t += 2)
        acc += sc[t] * Vc[(((size_t)b * Sn + t) * NHn + n) * HD + h];
    if (grp == 1) acc += sc[Sn] * v1[(size_t)b * NHHD + n * HD + h];
    oacc[grp][h] = acc;
    __syncthreads();
    if (tid < HD)
        out[(size_t)b * NHHD + n * HD + tid] = (oacc[0][tid] + oacc[1][tid]) * inv;
}

// ------------------- launch -------------------
extern "C" void kernel_launch(void* const* d_in, const int* in_sizes, int n_in,
                              void* d_out, int out_size)
{
    (void)in_sizes; (void)n_in; (void)out_size;
    const float* x  = (const float*)d_in[0];
    const float* xn = (const float*)d_in[1];
    const float* wq = (const float*)d_in[2];
    const float* wk = (const float*)d_in[3];
    const float* wv = (const float*)d_in[4];
    const float* wo = (const float*)d_in[5];
    float* out = (float*)d_out;

    float *q, *k, *v, *q1, *k1, *v1, *qkv1;
    __half *attnh, *xh, *wqh, *wkh, *wvh, *woh;
    cudaGetSymbolAddress((void**)&q,     g_q);
    cudaGetSymbolAddress((void**)&k,     g_k);
    cudaGetSymbolAddress((void**)&v,     g_v);
    cudaGetSymbolAddress((void**)&attnh, g_attnh);
    cudaGetSymbolAddress((void**)&xh,    g_xh);
    cudaGetSymbolAddress((void**)&wqh,   g_wqh);
    cudaGetSymbolAddress((void**)&wkh,   g_wkh);
    cudaGetSymbolAddress((void**)&wvh,   g_wvh);
    cudaGetSymbolAddress((void**)&woh,   g_woh);
    cudaGetSymbolAddress((void**)&q1,    g_q1);
    cudaGetSymbolAddress((void**)&k1,    g_k1);
    cudaGetSymbolAddress((void**)&v1,    g_v1);
    cudaGetSymbolAddress((void**)&qkv1,  g_qkv1);

    // 0. fp16 conversions: x (8M), wo (4M), transposed wq/wk/wv
    const int xn4 = (Bz * Sn * DM) / 4;
    const int wn4 = (DM * NHHD) / 4;
    conv_half_kernel<<<xn4 / 256, 256>>>(x,  xh,  xn4);
    conv_half_kernel<<<wn4 / 256, 256>>>(wo, woh, wn4);
    dim3 gtr(DM / 32, NHHD / 32, 3);
    transpose_half_kernel<<<gtr, 256>>>(wq, wk, wv, wqh, wkh, wvh);

    // fp16 GEMM smem: 3 stages x (A+B) words
    const int gsmem = 3 * STGW * (int)sizeof(uint32_t);  // 110,592
    cudaFuncSetAttribute(gemm_f16, cudaFuncAttributeMaxDynamicSharedMemorySize, gsmem);
    dim3 gproj(GN / 128, (Bz * Sn) / 128);  // (16, 32)

    // 1. prefill projections (fp16 tensor cores)
    gemm_f16<<<gproj, 256, gsmem>>>(xh, wqh, q);
    gemm_f16<<<gproj, 256, gsmem>>>(xh, wkh, k);
    gemm_f16<<<gproj, 256, gsmem>>>(xh, wvh, v);

    // 2. decode projections
    decode_zero_kernel<<<(Bz * NHHD + 255) / 256, 256>>>(q1, k1, v1);
    dim3 gdp(NHHD / 256, 16, 3);
    decode_proj_kernel<<<gdp, 256>>>(xn, wq, wk, wv, q1, k1, v1);

    // 3. prefill flash attention (fp16 tensor cores)
    const int fsmem = (FQ * QST + FK * QST + (FK / 2) * VST + FQ * PST) * (int)sizeof(uint32_t);
    cudaFuncSetAttribute(flash_f16_kernel,
                         cudaFuncAttributeMaxDynamicSharedMemorySize, fsmem);
    dim3 gattn(Sn / FQ, NHn, Bz);
    flash_f16_kernel<<<gattn, 256, fsmem>>>(q, k, v, attnh);

    // 4. decode attention
    dim3 gdatt(NHn, Bz);
    decode_attn_kernel<<<gdatt, 256>>>(k, v, q1, k1, v1, qkv1);

    // 5. output projections: out = attn @ wo^T (wo already [N,K]); decode tail
    gemm_f16<<<gproj, 256, gsmem>>>(attnh, woh, out);
    decode_outproj_kernel<<<DM / 8, 256>>>(qkv1, wo, out + (size_t)Bz * Sn * DM);
}